// round 6
// baseline (speedup 1.0000x reference)
#include <cuda_runtime.h>
#include <cstdint>

typedef unsigned int u32;

#define EPSBN 1e-5f
#define C1 512
#define C2 128
#define C3 32
#define HW 784
#define PTOT (64*HW)   // 50176

// ---------------- device scratch ----------------
__device__ u32   g_pmn[1040], g_pmx[1040];   // per-block min/max partials (encoded)
__device__ u32   g_mm[8];                    // [6,7] = a2 min/max atomics
__device__ float g_qp[12];                   // [0..2]=a1 [3..5]=w1 [6..8]=w2  (mn,s,rcp)
__device__ u32   g_wq1_32[C2*C1/4];          // w1 u8 packed [co][128]
__device__ int   g_ws1[C2];                  // per-co w1 index sums
__device__ u32   g_wq2c[C3*288];             // w2 u8 packed [co][tap*32+kg]  (co-major)
__device__ int   g_wts2[C3*9];               // per-(co,tap) w2 index sums
__device__ float g_a2[(size_t)PTOT*C2];      // relu(bn2(h)) fp32 NHWC (25.7MB)
__device__ u32   g_aq2[(size_t)PTOT*32];     // quantized a2 u8x4 NHWC (6.4MB)
__device__ int   g_rs2[PTOT];                // per-pixel a2 index sums

// ---------------- helpers ----------------
__device__ __forceinline__ u32 fenc(float f){
    u32 u = __float_as_uint(f);
    return (u & 0x80000000u) ? ~u : (u | 0x80000000u);
}
__device__ __forceinline__ float fdec(u32 e){
    return __uint_as_float((e & 0x80000000u) ? (e & 0x7fffffffu) : ~e);
}
__device__ __forceinline__ int qidx(float v, float mn, float s, float r){
    float t  = __fsub_rn(v, mn);
    float q0 = __fmul_rn(t, r);
    float q  = __fmaf_rn(__fmaf_rn(-s, q0, t), r, q0);
    int i = __float2int_rn(q);
    i = i < 0 ? 0 : i;
    return i > 255 ? 255 : i;
}
// u8 IMMA: D(16x8,s32) += A(16x32,u8,row) * B(32x8,u8,col)
__device__ __forceinline__ void imma(int* c, u32 a0, u32 a1, u32 a2, u32 a3, u32 b0, u32 b1){
    asm volatile("mma.sync.aligned.m16n8k32.row.col.s32.u8.u8.s32 "
                 "{%0,%1,%2,%3},{%4,%5,%6,%7},{%8,%9},{%0,%1,%2,%3};"
                 : "+r"(c[0]), "+r"(c[1]), "+r"(c[2]), "+r"(c[3])
                 : "r"(a0), "r"(a1), "r"(a2), "r"(a3), "r"(b0), "r"(b1));
}

// ---------------- K1: all min/max partials ----------------
__global__ void k_mm(const float* __restrict__ x, const float* __restrict__ g1,
                     const float* __restrict__ b1, const float* __restrict__ m1,
                     const float* __restrict__ v1, const float* __restrict__ w1,
                     const float* __restrict__ w2){
    __shared__ float sinv[C1], sbias[C1];
    __shared__ u32 wmin[8], wmax[8];
    int b = blockIdx.x, t = threadIdx.x;
    float lmin = 3.4e38f, lmax = -3.4e38f;
    if (b < 1024){
        for (int c = t; c < C1; c += 256){
            float iv = __fdiv_rn(g1[c], __fsqrt_rn(v1[c] + EPSBN));
            sinv[c]  = iv;
            sbias[c] = __fmaf_rn(-m1[c], iv, b1[c]);
        }
        __syncthreads();
        const float4* x4 = (const float4*)x;
        const int tot = 64*C1*HW/4;
        const int step = 1024*256;
        for (int i = b*256 + t; i < tot; i += 4*step){
            int i1 = i + step, i2 = i + 2*step, i3 = i + 3*step;
            bool p1 = i1 < tot, p2 = i2 < tot, p3 = i3 < tot;
            float4 u0 = x4[i];
            float4 u1 = p1 ? x4[i1] : u0;
            float4 u2 = p2 ? x4[i2] : u0;
            float4 u3 = p3 ? x4[i3] : u0;
            int c0i = (i /196) & (C1-1);
            int c1i = (i1/196) & (C1-1);
            int c2i = (i2/196) & (C1-1);
            int c3i = (i3/196) & (C1-1);
            float iv0 = sinv[c0i], bb0 = sbias[c0i];
            float iv1 = sinv[c1i], bb1 = sbias[c1i];
            float iv2 = sinv[c2i], bb2 = sbias[c2i];
            float iv3 = sinv[c3i], bb3 = sbias[c3i];
            #define MM4(U,IV,BB) {                                            \
                float a0 = fmaxf(__fmaf_rn(U.x, IV, BB), 0.f);                \
                float a1 = fmaxf(__fmaf_rn(U.y, IV, BB), 0.f);                \
                float a2 = fmaxf(__fmaf_rn(U.z, IV, BB), 0.f);                \
                float a3 = fmaxf(__fmaf_rn(U.w, IV, BB), 0.f);                \
                lmax = fmaxf(lmax, fmaxf(fmaxf(a0,a1), fmaxf(a2,a3)));        \
                lmin = fminf(lmin, fminf(fminf(a0,a1), fminf(a2,a3))); }
            MM4(u0, iv0, bb0);
            if (p1) MM4(u1, iv1, bb1);
            if (p2) MM4(u2, iv2, bb2);
            if (p3) MM4(u3, iv3, bb3);
            #undef MM4
        }
    } else if (b < 1032){
        int s0 = (b-1024)*8192;
        for (int i = t; i < 8192; i += 256){
            float v = w1[s0+i];
            lmin = fminf(lmin, v); lmax = fmaxf(lmax, v);
        }
    } else {
        int s0 = (b-1032)*4608;
        for (int i = t; i < 4608; i += 256){
            float v = w2[s0+i];
            lmin = fminf(lmin, v); lmax = fmaxf(lmax, v);
        }
    }
    u32 emin = __reduce_min_sync(0xffffffffu, fenc(lmin));
    u32 emax = __reduce_max_sync(0xffffffffu, fenc(lmax));
    if ((t & 31) == 0){ wmin[t>>5] = emin; wmax[t>>5] = emax; }
    __syncthreads();
    if (t == 0){
        u32 mn = wmin[0], mx = wmax[0];
        for (int i = 1; i < 8; i++){ mn = min(mn, wmin[i]); mx = max(mx, wmax[i]); }
        g_pmn[b] = mn; g_pmx[b] = mx;
    }
}

// ---------------- K2: params + weight quantization ----------------
__global__ void k_prep(const float* __restrict__ w1, const float* __restrict__ w2){
    __shared__ int ss[9];
    __shared__ u32 smn[8], smx[8];
    int b = blockIdx.x, t = threadIdx.x;
    if (b < 128){
        u32 emn = g_pmn[1024], emx = g_pmx[1024];
        #pragma unroll
        for (int i = 1; i < 8; i++){ emn = min(emn, g_pmn[1024+i]); emx = max(emx, g_pmx[1024+i]); }
        float mn = fdec(emn), mx = fdec(emx);
        float s = fmaxf(__fdiv_rn(mx - mn, 255.0f), 1e-8f), r = __frcp_rn(s);
        int co = b;
        int lsum = 0;
        if (t < 128){
            u32 pack = 0;
            #pragma unroll
            for (int j = 0; j < 4; j++){
                int q = qidx(w1[co*C1 + 4*t + j], mn, s, r);
                pack |= (u32)q << (8*j);
                lsum += q;
            }
            g_wq1_32[co*128 + t] = pack;
        }
        lsum = __reduce_add_sync(0xffffffffu, lsum);
        if ((t & 31) == 0) ss[t>>5] = lsum;
        __syncthreads();
        if (t == 0){
            g_ws1[co] = ss[0] + ss[1] + ss[2] + ss[3];
            if (co == 0){ g_qp[3]=mn; g_qp[4]=s; g_qp[5]=r; }
        }
    } else if (b < 160){
        int co = b - 128;
        u32 emn = g_pmn[1032], emx = g_pmx[1032];
        #pragma unroll
        for (int i = 1; i < 8; i++){ emn = min(emn, g_pmn[1032+i]); emx = max(emx, g_pmx[1032+i]); }
        float mn = fdec(emn), mx = fdec(emx);
        float s = fmaxf(__fdiv_rn(mx - mn, 255.0f), 1e-8f), r = __frcp_rn(s);
        if (t < 9) ss[t] = 0;
        __syncthreads();
        for (int f = t; f < 288; f += 256){
            int tap = f >> 5, kg = f & 31;
            u32 pack = 0; int psum = 0;
            #pragma unroll
            for (int j = 0; j < 4; j++){
                int ci = kg*4 + j;
                int q = qidx(w2[co*1152 + ci*9 + tap], mn, s, r);
                pack |= (u32)q << (8*j);
                psum += q;
            }
            g_wq2c[co*288 + f] = pack;
            atomicAdd(&ss[tap], psum);
        }
        __syncthreads();
        if (t < 9) g_wts2[co*9 + t] = ss[t];
        if (t == 0 && co == 0){ g_qp[6]=mn; g_qp[7]=s; g_qp[8]=r; }
    } else {
        u32 emn = 0xFFFFFFFFu, emx = 0u;
        for (int i = t; i < 1024; i += 256){ emn = min(emn, g_pmn[i]); emx = max(emx, g_pmx[i]); }
        emn = __reduce_min_sync(0xffffffffu, emn);
        emx = __reduce_max_sync(0xffffffffu, emx);
        if ((t & 31) == 0){ smn[t>>5] = emn; smx[t>>5] = emx; }
        __syncthreads();
        if (t == 0){
            u32 mn2 = smn[0], mx2 = smx[0];
            for (int i = 1; i < 8; i++){ mn2 = min(mn2, smn[i]); mx2 = max(mx2, smx[i]); }
            float mn = fdec(mn2), mx = fdec(mx2);
            float s = fmaxf(__fdiv_rn(mx - mn, 255.0f), 1e-8f);
            g_qp[0] = mn; g_qp[1] = s; g_qp[2] = __frcp_rn(s);
            g_mm[6] = 0xFFFFFFFFu; g_mm[7] = 0u;
        }
    }
}

// ---------------- K3: conv1 via IMMA, 64px tiles, 2 CTA/SM ----------------
#define AS_U32   (64*132)         // 8448
#define WS_U32   (128*132)        // 16896
#define SP_U32   (AS_U32+WS_U32)  // 25344
#define DYN_SMEM (SP_U32*4 + 6400)

__global__ __launch_bounds__(256,2) void k_conv1(
    const float* __restrict__ x,
    const float* __restrict__ g1, const float* __restrict__ b1,
    const float* __restrict__ m1, const float* __restrict__ v1,
    const float* __restrict__ g2, const float* __restrict__ b2,
    const float* __restrict__ m2, const float* __restrict__ v2)
{
    extern __shared__ __align__(16) u32 sm[];
    u32* As = sm;
    u32* Ws = sm + AS_U32;
    float* inv1 = (float*)(sm + SP_U32);
    float* bia1 = inv1 + 512;
    float* inv2 = bia1 + 512;
    float* bia2 = inv2 + 128;
    int*   ws_s = (int*)(bia2 + 128);
    int*   rs_s = ws_s + 128;
    u32*   red  = (u32*)(rs_s + 64);

    int tid = threadIdx.x, wid = tid >> 5, lane = tid & 31;
    int g = lane >> 2, tg = lane & 3;
    int p0 = blockIdx.x * 64;

    for (int c = tid; c < C1; c += 256){
        float iv = __fdiv_rn(g1[c], __fsqrt_rn(v1[c] + EPSBN));
        inv1[c] = iv; bia1[c] = __fmaf_rn(-m1[c], iv, b1[c]);
    }
    if (tid < 128){
        float iv = __fdiv_rn(g2[tid], __fsqrt_rn(v2[tid] + EPSBN));
        inv2[tid] = iv; bia2[tid] = __fmaf_rn(-m2[tid], iv, b2[tid]);
        ws_s[tid] = g_ws1[tid];
    }
    if (tid < 64) rs_s[tid] = 0;
    #pragma unroll
    for (int it = 0; it < 64; it++){
        int f = it*256 + tid;
        Ws[(f>>7)*132 + (f&127)] = g_wq1_32[f];
    }
    __syncthreads();

    float mnA = g_qp[0], sA = g_qp[1], rA = g_qp[2];

    // ---- build quantized u8 activation tile A [64px][512ci] ----
    {
        int px = tid & 63, q4 = tid >> 6;
        int p = p0 + px;
        u32 base = (u32)((p/HW)*(C1*HW) + (p%HW));
        int ci0 = q4 * 128;
        int lsum = 0;
        #pragma unroll 8
        for (int m = 0; m < 32; m++){
            int ci = ci0 + 4*m;
            float x0 = x[base + (u32)(ci+0)*HW];
            float x1 = x[base + (u32)(ci+1)*HW];
            float x2 = x[base + (u32)(ci+2)*HW];
            float x3 = x[base + (u32)(ci+3)*HW];
            float a0 = fmaxf(__fmaf_rn(x0, inv1[ci+0], bia1[ci+0]), 0.f);
            float a1 = fmaxf(__fmaf_rn(x1, inv1[ci+1], bia1[ci+1]), 0.f);
            float a2 = fmaxf(__fmaf_rn(x2, inv1[ci+2], bia1[ci+2]), 0.f);
            float a3 = fmaxf(__fmaf_rn(x3, inv1[ci+3], bia1[ci+3]), 0.f);
            int q0 = qidx(a0, mnA, sA, rA);
            int q1 = qidx(a1, mnA, sA, rA);
            int q2 = qidx(a2, mnA, sA, rA);
            int q3 = qidx(a3, mnA, sA, rA);
            u32 pack = (u32)q0 | ((u32)q1<<8) | ((u32)q2<<16) | ((u32)q3<<24);
            lsum += q0 + q1 + q2 + q3;
            As[px*132 + q4*32 + m] = pack;
        }
        atomicAdd(&rs_s[px], lsum);
    }
    __syncthreads();

    // ---- IMMA mainloop: warp computes 16px x 64co ----
    int r0 = (wid >> 1) * 16;
    int c0 = (wid & 1) * 64;
    int acc[8][4];
    #pragma unroll
    for (int ct = 0; ct < 8; ct++)
        #pragma unroll
        for (int d = 0; d < 4; d++) acc[ct][d] = 0;

    #pragma unroll 4
    for (int kk = 0; kk < 16; kk++){
        int kg0 = kk*8;
        u32 a0 = As[(r0 + g)*132     + kg0 + tg];
        u32 a1 = As[(r0 + 8 + g)*132 + kg0 + tg];
        u32 a2 = As[(r0 + g)*132     + kg0 + 4 + tg];
        u32 a3 = As[(r0 + 8 + g)*132 + kg0 + 4 + tg];
        #pragma unroll
        for (int ct = 0; ct < 8; ct++){
            int co = c0 + ct*8 + g;
            u32 b0 = Ws[co*132 + kg0 + tg];
            u32 b1 = Ws[co*132 + kg0 + 4 + tg];
            imma(acc[ct], a0, a1, a2, a3, b0, b1);
        }
    }
    __syncthreads();

    // ---- epilogue ----
    float mnW = g_qp[3], sW = g_qp[4];
    float SS = sA * sW;
    float c0f = 512.0f * mnA * mnW;
    float* fo = (float*)As;
    float lmin = 3.4e38f, lmax = -3.4e38f;
    #pragma unroll
    for (int hh = 0; hh < 2; hh++){
        int px = r0 + hh*8 + g;
        float t1 = __fmaf_rn(sA*mnW, (float)rs_s[px], c0f);
        #pragma unroll
        for (int ct = 0; ct < 8; ct++){
            #pragma unroll
            for (int e = 0; e < 2; e++){
                int co = c0 + ct*8 + 2*tg + e;
                float h = __fmaf_rn(SS, (float)acc[ct][hh*2+e],
                          __fmaf_rn(mnA*sW, (float)ws_s[co], t1));
                float a2v = fmaxf(__fmaf_rn(h, inv2[co], bia2[co]), 0.f);
                fo[px*132 + co] = a2v;
                lmin = fminf(lmin, a2v); lmax = fmaxf(lmax, a2v);
            }
        }
    }
    u32 emin = __reduce_min_sync(0xffffffffu, fenc(lmin));
    u32 emax = __reduce_max_sync(0xffffffffu, fenc(lmax));
    if (lane == 0){ red[wid] = emin; red[8+wid] = emax; }
    __syncthreads();
    if (tid == 0){
        u32 mn = red[0], mx = red[8];
        for (int i = 1; i < 8; i++){ mn = min(mn, red[i]); mx = max(mx, red[8+i]); }
        atomicMin(&g_mm[6], mn); atomicMax(&g_mm[7], mx);
    }
    #pragma unroll
    for (int it = 0; it < 8; it++){
        int f = it*256 + tid;
        int pxi = f >> 5, j = f & 31;
        float4 v = *(float4*)&fo[pxi*132 + j*4];
        *(float4*)&g_a2[(size_t)(p0 + pxi)*C2 + j*4] = v;
    }
}

// ---------------- K4: quantize a2 (2 pixels per warp) ----------------
__global__ void k_qa2(){
    int warp = threadIdx.x >> 5, lane = threadIdx.x & 31;
    int p = blockIdx.x*16 + warp*2;
    float mn = fdec(g_mm[6]), mx = fdec(g_mm[7]);
    float s = fmaxf(__fdiv_rn(mx - mn, 255.0f), 1e-8f), r = __frcp_rn(s);
    const float4* a0 = (const float4*)&g_a2[(size_t)p*C2];
    const float4* a1 = (const float4*)&g_a2[(size_t)(p+1)*C2];
    float4 v0 = a0[lane];
    float4 v1 = a1[lane];
    int q00 = qidx(v0.x, mn, s, r), q01 = qidx(v0.y, mn, s, r);
    int q02 = qidx(v0.z, mn, s, r), q03 = qidx(v0.w, mn, s, r);
    int q10 = qidx(v1.x, mn, s, r), q11 = qidx(v1.y, mn, s, r);
    int q12 = qidx(v1.z, mn, s, r), q13 = qidx(v1.w, mn, s, r);
    g_aq2[(size_t)p*32 + lane]     = (u32)q00 | ((u32)q01<<8) | ((u32)q02<<16) | ((u32)q03<<24);
    g_aq2[(size_t)(p+1)*32 + lane] = (u32)q10 | ((u32)q11<<8) | ((u32)q12<<16) | ((u32)q13<<24);
    int s0 = __reduce_add_sync(0xffffffffu, q00+q01+q02+q03);
    int s1 = __reduce_add_sync(0xffffffffu, q10+q11+q12+q13);
    if (lane == 0){ g_rs2[p] = s0; g_rs2[p+1] = s1; }
}

// ---------------- K5: 3x3 conv via IMMA, 2 output rows per block ----------------
#define AT_ROWS 134   // 4*30 rows + slack for discarded m=28..31 fragment reads
__global__ __launch_bounds__(256) void k_conv2(float* __restrict__ out){
    __shared__ u32 Ws[32*292];          // [co][288 words], stride 292
    __shared__ u32 a_t[AT_ROWS*36];     // [4 rows x 30 halo cols][32 words], stride 36
    __shared__ int   rs_s[4*30];
    __shared__ float rsum_p[2][28];
    __shared__ float wvL[2][32], wvM[2][32], wvR[2][32];

    int tid = threadIdx.x;
    int b = blockIdx.x;
    int n = b / 14, hp = b % 14, h0 = hp*2;
    int wid = tid >> 5, lane = tid & 31;
    int g = lane >> 2, tg = lane & 3;

    for (int f = tid; f < 9216; f += 256){
        int co = f / 288, k = f - co*288;
        Ws[co*292 + k] = g_wq2c[f];
    }
    for (int f = tid; f < AT_ROWS*36; f += 256) a_t[f] = 0;
    if (tid < 120) rs_s[tid] = 0;
    __syncthreads();
    // fill 4 input rows (h0-1 .. h0+2) with halo col offset +1
    for (int f = tid; f < 4*28*32; f += 256){
        int rr = f / (28*32); int rem = f - rr*28*32;
        int col = rem >> 5, k = rem & 31;
        int gh = h0 + rr - 1;
        if ((unsigned)gh < 28u)
            a_t[(rr*30 + col + 1)*36 + k] = g_aq2[(size_t)(n*HW + gh*28 + col)*32 + k];
    }
    if (tid < 112){
        int rr = tid / 28, col = tid % 28;
        int gh = h0 + rr - 1;
        if ((unsigned)gh < 28u) rs_s[rr*30 + col + 1] = g_rs2[n*HW + gh*28 + col];
    }
    __syncthreads();

    if (tid < 56){
        int orow = tid / 28, px = tid % 28;
        int ssum = 0;
        #pragma unroll
        for (int rr = 0; rr < 3; rr++)
            #pragma unroll
            for (int dw = 0; dw < 3; dw++)
                ssum += rs_s[(orow + rr)*30 + px + dw];
        rsum_p[orow][px] = (float)ssum;
    }
    if (tid >= 64 && tid < 128){
        int t2 = tid - 64;
        int orow = t2 >> 5, co = t2 & 31;
        int h = h0 + orow;
        float m = 0.f, l = 0.f, r_ = 0.f;
        #pragma unroll
        for (int rr = 0; rr < 3; rr++){
            if ((unsigned)(h + rr - 1) < 28u){
                float w0 = (float)g_wts2[co*9 + rr*3 + 0];
                float w1 = (float)g_wts2[co*9 + rr*3 + 1];
                float w2 = (float)g_wts2[co*9 + rr*3 + 2];
                m  += w0 + w1 + w2;
                l  += w1 + w2;
                r_ += w0 + w1;
            }
        }
        wvM[orow][co] = m; wvL[orow][co] = l; wvR[orow][co] = r_;
    }
    __syncthreads();

    // ---- IMMA: warp (orow, cb) handles output row h0+orow, co block cb*8 ----
    int orow = wid >> 2, cb = wid & 3;
    int acc[2][4];
    #pragma unroll
    for (int i = 0; i < 2; i++)
        #pragma unroll
        for (int d = 0; d < 4; d++) acc[i][d] = 0;

    #pragma unroll
    for (int s = 0; s < 36; s++){
        int tap = s >> 2;
        int rr = tap / 3, dw = tap - rr*3;
        int w0 = (s & 3)*8 + tg;
        u32 b0 = Ws[(cb*8 + g)*292 + s*8 + tg];
        u32 b1 = Ws[(cb*8 + g)*292 + s*8 + 4 + tg];
        int rbase = (orow + rr)*30 + dw;
        u32 a0 = a_t[(rbase + g)*36      + w0];
        u32 a1 = a_t[(rbase + 8 + g)*36  + w0];
        u32 a2 = a_t[(rbase + g)*36      + w0 + 4];
        u32 a3 = a_t[(rbase + 8 + g)*36  + w0 + 4];
        imma(acc[0], a0, a1, a2, a3, b0, b1);
        u32 c0 = a_t[(rbase + 16 + g)*36 + w0];
        u32 c1 = a_t[(rbase + 24 + g)*36 + w0];
        u32 c2 = a_t[(rbase + 16 + g)*36 + w0 + 4];
        u32 c3 = a_t[(rbase + 24 + g)*36 + w0 + 4];
        imma(acc[1], c0, c1, c2, c3, b0, b1);
    }

    // ---- epilogue ----
    float mnA2 = fdec(g_mm[6]), mxA2 = fdec(g_mm[7]);
    float sA2 = fmaxf(__fdiv_rn(mxA2 - mnA2, 255.0f), 1e-8f);
    float mnW = g_qp[6], sW = g_qp[7];
    int h = h0 + orow;
    float rowv = 0.f;
    #pragma unroll
    for (int rr = 0; rr < 3; rr++) rowv += ((unsigned)(h + rr - 1) < 28u) ? 1.f : 0.f;
    float SS = sA2 * sW;
    #pragma unroll
    for (int ti = 0; ti < 2; ti++){
        #pragma unroll
        for (int hh = 0; hh < 2; hh++){
            int px = ti*16 + hh*8 + g;
            if (px < 28){
                float colv = (px == 0 || px == 27) ? 2.f : 3.f;
                float nv   = rowv * colv * 128.0f;
                float rp   = rsum_p[orow][px];
                #pragma unroll
                for (int e = 0; e < 2; e++){
                    int co = cb*8 + 2*tg + e;
                    float wvv = (px == 0) ? wvL[orow][co] : ((px == 27) ? wvR[orow][co] : wvM[orow][co]);
                    float o = __fmaf_rn(SS, (float)acc[ti][hh*2+e],
                              __fmaf_rn(sA2*mnW, rp,
                              __fmaf_rn(mnA2*sW, wvv, mnA2*mnW*nv)));
                    out[((size_t)n*32 + co)*HW + h*28 + px] = o;
                }
            }
        }
    }
}

extern "C" void kernel_launch(void* const* d_in, const int* in_sizes, int n_in,
                              void* d_out, int out_size){
    const float* x  = (const float*)d_in[0];
    const float* g1 = (const float*)d_in[1];
    const float* b1 = (const float*)d_in[2];
    const float* m1 = (const float*)d_in[3];
    const float* v1 = (const float*)d_in[4];
    const float* w1 = (const float*)d_in[5];
    const float* g2 = (const float*)d_in[6];
    const float* b2 = (const float*)d_in[7];
    const float* m2 = (const float*)d_in[8];
    const float* v2 = (const float*)d_in[9];
    const float* w2 = (const float*)d_in[10];
    float* out = (float*)d_out;

    cudaFuncSetAttribute(k_conv1, cudaFuncAttributeMaxDynamicSharedMemorySize, DYN_SMEM);

    k_mm   <<<1040, 256>>>(x, g1, b1, m1, v1, w1, w2);
    k_prep <<<161, 256>>>(w1, w2);
    k_conv1<<<784, 256, DYN_SMEM>>>(x, g1, b1, m1, v1, g2, b2, m2, v2);
    k_qa2  <<<3136, 256>>>();
    k_conv2<<<896, 256>>>(out);
}

// round 7
// speedup vs baseline: 1.1774x; 1.1774x over previous
#include <cuda_runtime.h>
#include <cstdint>

typedef unsigned int u32;

#define EPSBN 1e-5f
#define C1 512
#define C2 128
#define C3 32
#define HW 784
#define PTOT (64*HW)     // 50176
#define NPLANES (64*C1)  // 32768

// ---------------- device scratch ----------------
__device__ float g_plmn[NPLANES], g_plmx[NPLANES]; // per-(n,c)-plane raw x min/max
__device__ u32   g_wpmn[16], g_wpmx[16];           // w1 (0..7) / w2 (8..15) encoded partials
__device__ u32   g_mm[8];                          // [6,7] = a2 min/max atomics
__device__ float g_qp[12];                         // [0..2]=a1 [3..5]=w1 [6..8]=w2  (mn,s,rcp)
__device__ u32   g_wq1_32[C2*C1/4];                // w1 u8 packed [co][128]
__device__ int   g_ws1[C2];                        // per-co w1 index sums
__device__ u32   g_wq2c[C3*288];                   // w2 u8 packed [co][tap*32+kg]  (co-major)
__device__ int   g_wts2[C3*9];                     // per-(co,tap) w2 index sums
__device__ float g_a2[(size_t)PTOT*C2];            // relu(bn2(h)) fp32 NHWC (25.7MB)
__device__ u32   g_aq2[(size_t)PTOT*32];           // quantized a2 u8x4 NHWC (6.4MB)
__device__ int   g_rs2[PTOT];                      // per-pixel a2 index sums

// ---------------- helpers ----------------
__device__ __forceinline__ u32 fenc(float f){
    u32 u = __float_as_uint(f);
    return (u & 0x80000000u) ? ~u : (u | 0x80000000u);
}
__device__ __forceinline__ float fdec(u32 e){
    return __uint_as_float((e & 0x80000000u) ? (e & 0x7fffffffu) : ~e);
}
__device__ __forceinline__ int qidx(float v, float mn, float s, float r){
    float t  = __fsub_rn(v, mn);
    float q0 = __fmul_rn(t, r);
    float q  = __fmaf_rn(__fmaf_rn(-s, q0, t), r, q0);
    int i = __float2int_rn(q);
    i = i < 0 ? 0 : i;
    return i > 255 ? 255 : i;
}
// u8 IMMA: D(16x8,s32) += A(16x32,u8,row) * B(32x8,u8,col)
__device__ __forceinline__ void imma(int* c, u32 a0, u32 a1, u32 a2, u32 a3, u32 b0, u32 b1){
    asm volatile("mma.sync.aligned.m16n8k32.row.col.s32.u8.u8.s32 "
                 "{%0,%1,%2,%3},{%4,%5,%6,%7},{%8,%9},{%0,%1,%2,%3};"
                 : "+r"(c[0]), "+r"(c[1]), "+r"(c[2]), "+r"(c[3])
                 : "r"(a0), "r"(a1), "r"(a2), "r"(a3), "r"(b0), "r"(b1));
}

// ---------------- K1: raw min/max partials ----------------
// b < 2048: 16 contiguous (n,c) planes of x, pure streaming min/max
// b in [2048,2056): w1 chunk;  b in [2056,2064): w2 chunk
__global__ void k_mm(const float* __restrict__ x,
                     const float* __restrict__ w1, const float* __restrict__ w2){
    int b = blockIdx.x, t = threadIdx.x;
    if (b < 2048){
        int plane = b*16 + (t >> 4);
        int l16 = t & 15;
        const float4* p4 = (const float4*)x + (size_t)plane*196;
        float mn = 3.4e38f, mx = -3.4e38f;
        #pragma unroll
        for (int k = 0; k < 12; k++){
            float4 v = p4[l16 + k*16];
            mn = fminf(mn, fminf(fminf(v.x, v.y), fminf(v.z, v.w)));
            mx = fmaxf(mx, fmaxf(fmaxf(v.x, v.y), fmaxf(v.z, v.w)));
        }
        if (l16 < 4){
            float4 v = p4[192 + l16];
            mn = fminf(mn, fminf(fminf(v.x, v.y), fminf(v.z, v.w)));
            mx = fmaxf(mx, fmaxf(fmaxf(v.x, v.y), fmaxf(v.z, v.w)));
        }
        #pragma unroll
        for (int off = 8; off; off >>= 1){
            mn = fminf(mn, __shfl_xor_sync(0xffffffffu, mn, off));
            mx = fmaxf(mx, __shfl_xor_sync(0xffffffffu, mx, off));
        }
        if (l16 == 0){ g_plmn[plane] = mn; g_plmx[plane] = mx; }
    } else {
        __shared__ u32 wmin[8], wmax[8];
        float lmin = 3.4e38f, lmax = -3.4e38f;
        int slot;
        if (b < 2056){
            slot = b - 2048;
            int s0 = slot*8192;
            for (int i = t; i < 8192; i += 256){
                float v = w1[s0+i];
                lmin = fminf(lmin, v); lmax = fmaxf(lmax, v);
            }
        } else {
            slot = 8 + (b - 2056);
            int s0 = (b-2056)*4608;
            for (int i = t; i < 4608; i += 256){
                float v = w2[s0+i];
                lmin = fminf(lmin, v); lmax = fmaxf(lmax, v);
            }
        }
        u32 emin = __reduce_min_sync(0xffffffffu, fenc(lmin));
        u32 emax = __reduce_max_sync(0xffffffffu, fenc(lmax));
        if ((t & 31) == 0){ wmin[t>>5] = emin; wmax[t>>5] = emax; }
        __syncthreads();
        if (t == 0){
            u32 mn = wmin[0], mx = wmax[0];
            for (int i = 1; i < 8; i++){ mn = min(mn, wmin[i]); mx = max(mx, wmax[i]); }
            g_wpmn[slot] = mn; g_wpmx[slot] = mx;
        }
    }
}

// ---------------- K2: params + weight quantization ----------------
__global__ void k_prep(const float* __restrict__ w1, const float* __restrict__ w2,
                       const float* __restrict__ g1, const float* __restrict__ b1,
                       const float* __restrict__ m1, const float* __restrict__ v1){
    __shared__ int ss[9];
    __shared__ float red[64];
    int b = blockIdx.x, t = threadIdx.x;
    if (b < 128){
        u32 emn = g_wpmn[0], emx = g_wpmx[0];
        #pragma unroll
        for (int i = 1; i < 8; i++){ emn = min(emn, g_wpmn[i]); emx = max(emx, g_wpmx[i]); }
        float mn = fdec(emn), mx = fdec(emx);
        float s = fmaxf(__fdiv_rn(mx - mn, 255.0f), 1e-8f), r = __frcp_rn(s);
        int co = b;
        int lsum = 0;
        if (t < 128){
            u32 pack = 0;
            #pragma unroll
            for (int j = 0; j < 4; j++){
                int q = qidx(w1[co*C1 + 4*t + j], mn, s, r);
                pack |= (u32)q << (8*j);
                lsum += q;
            }
            g_wq1_32[co*128 + t] = pack;
        }
        lsum = __reduce_add_sync(0xffffffffu, lsum);
        if ((t & 31) == 0) ss[t>>5] = lsum;
        __syncthreads();
        if (t == 0){
            g_ws1[co] = ss[0] + ss[1] + ss[2] + ss[3];
            if (co == 0){ g_qp[3]=mn; g_qp[4]=s; g_qp[5]=r; }
        }
    } else if (b < 160){
        int co = b - 128;
        u32 emn = g_wpmn[8], emx = g_wpmx[8];
        #pragma unroll
        for (int i = 1; i < 8; i++){ emn = min(emn, g_wpmn[8+i]); emx = max(emx, g_wpmx[8+i]); }
        float mn = fdec(emn), mx = fdec(emx);
        float s = fmaxf(__fdiv_rn(mx - mn, 255.0f), 1e-8f), r = __frcp_rn(s);
        if (t < 9) ss[t] = 0;
        __syncthreads();
        for (int f = t; f < 288; f += 256){
            int tap = f >> 5, kg = f & 31;
            u32 pack = 0; int psum = 0;
            #pragma unroll
            for (int j = 0; j < 4; j++){
                int ci = kg*4 + j;
                int q = qidx(w2[co*1152 + ci*9 + tap], mn, s, r);
                pack |= (u32)q << (8*j);
                psum += q;
            }
            g_wq2c[co*288 + f] = pack;
            atomicAdd(&ss[tap], psum);
        }
        __syncthreads();
        if (t < 9) g_wts2[co*9 + t] = ss[t];
        if (t == 0 && co == 0){ g_qp[6]=mn; g_qp[7]=s; g_qp[8]=r; }
    } else {
        // a1 params: apply monotone bn1+relu transform to per-plane extremes
        __shared__ float sinv[C1], sbias[C1];
        for (int c = t; c < C1; c += 256){
            float iv = __fdiv_rn(g1[c], __fsqrt_rn(v1[c] + EPSBN));
            sinv[c]  = iv;
            sbias[c] = __fmaf_rn(-m1[c], iv, b1[c]);
        }
        __syncthreads();
        float gmn = 3.4e38f, gmx = -3.4e38f;
        for (int p = t; p < NPLANES; p += 256){
            int c = p & (C1-1);
            float iv = sinv[c], bb = sbias[c];
            float v0 = __fmaf_rn(iv, g_plmn[p], bb);
            float v1_ = __fmaf_rn(iv, g_plmx[p], bb);
            float lo = fmaxf(fminf(v0, v1_), 0.f);
            float hi = fmaxf(fmaxf(v0, v1_), 0.f);
            gmn = fminf(gmn, lo);
            gmx = fmaxf(gmx, hi);
        }
        #pragma unroll
        for (int off = 16; off; off >>= 1){
            gmn = fminf(gmn, __shfl_xor_sync(0xffffffffu, gmn, off));
            gmx = fmaxf(gmx, __shfl_xor_sync(0xffffffffu, gmx, off));
        }
        if ((t & 31) == 0){ red[t>>5] = gmn; red[32 + (t>>5)] = gmx; }
        __syncthreads();
        if (t == 0){
            float mn = red[0], mx = red[32];
            for (int i = 1; i < 8; i++){ mn = fminf(mn, red[i]); mx = fmaxf(mx, red[32+i]); }
            float s = fmaxf(__fdiv_rn(mx - mn, 255.0f), 1e-8f);
            g_qp[0] = mn; g_qp[1] = s; g_qp[2] = __frcp_rn(s);
            g_mm[6] = 0xFFFFFFFFu; g_mm[7] = 0u;
        }
    }
}

// ---------------- K3: conv1 via IMMA, 64px tiles, 2 CTA/SM ----------------
#define AS_U32   (64*132)         // 8448
#define WS_U32   (128*132)        // 16896
#define SP_U32   (AS_U32+WS_U32)  // 25344
#define DYN_SMEM (SP_U32*4 + 6400)

__global__ __launch_bounds__(256,2) void k_conv1(
    const float* __restrict__ x,
    const float* __restrict__ g1, const float* __restrict__ b1,
    const float* __restrict__ m1, const float* __restrict__ v1,
    const float* __restrict__ g2, const float* __restrict__ b2,
    const float* __restrict__ m2, const float* __restrict__ v2)
{
    extern __shared__ __align__(16) u32 sm[];
    u32* As = sm;
    u32* Ws = sm + AS_U32;
    float* inv1 = (float*)(sm + SP_U32);
    float* bia1 = inv1 + 512;
    float* inv2 = bia1 + 512;
    float* bia2 = inv2 + 128;
    int*   ws_s = (int*)(bia2 + 128);
    int*   rs_s = ws_s + 128;
    u32*   red  = (u32*)(rs_s + 64);

    int tid = threadIdx.x, wid = tid >> 5, lane = tid & 31;
    int g = lane >> 2, tg = lane & 3;
    int p0 = blockIdx.x * 64;

    for (int c = tid; c < C1; c += 256){
        float iv = __fdiv_rn(g1[c], __fsqrt_rn(v1[c] + EPSBN));
        inv1[c] = iv; bia1[c] = __fmaf_rn(-m1[c], iv, b1[c]);
    }
    if (tid < 128){
        float iv = __fdiv_rn(g2[tid], __fsqrt_rn(v2[tid] + EPSBN));
        inv2[tid] = iv; bia2[tid] = __fmaf_rn(-m2[tid], iv, b2[tid]);
        ws_s[tid] = g_ws1[tid];
    }
    if (tid < 64) rs_s[tid] = 0;
    #pragma unroll
    for (int it = 0; it < 64; it++){
        int f = it*256 + tid;
        Ws[(f>>7)*132 + (f&127)] = g_wq1_32[f];
    }
    __syncthreads();

    float mnA = g_qp[0], sA = g_qp[1], rA = g_qp[2];

    // ---- build quantized u8 activation tile A [64px][512ci] ----
    {
        int px = tid & 63, q4 = tid >> 6;
        int p = p0 + px;
        u32 base = (u32)((p/HW)*(C1*HW) + (p%HW));
        int ci0 = q4 * 128;
        int lsum = 0;
        #pragma unroll 4
        for (int m = 0; m < 32; m++){
            int ci = ci0 + 4*m;
            u32 pack = 0;
            #pragma unroll
            for (int j = 0; j < 4; j++){
                float xv = x[base + (u32)(ci+j)*HW];
                float a = fmaxf(__fmaf_rn(xv, inv1[ci+j], bia1[ci+j]), 0.f);
                int q = qidx(a, mnA, sA, rA);
                pack |= (u32)q << (8*j);
                lsum += q;
            }
            As[px*132 + q4*32 + m] = pack;
        }
        atomicAdd(&rs_s[px], lsum);
    }
    __syncthreads();

    // ---- IMMA mainloop: warp computes 16px x 64co ----
    int r0 = (wid >> 1) * 16;
    int c0 = (wid & 1) * 64;
    int acc[8][4];
    #pragma unroll
    for (int ct = 0; ct < 8; ct++)
        #pragma unroll
        for (int d = 0; d < 4; d++) acc[ct][d] = 0;

    #pragma unroll 4
    for (int kk = 0; kk < 16; kk++){
        int kg0 = kk*8;
        u32 a0 = As[(r0 + g)*132     + kg0 + tg];
        u32 a1 = As[(r0 + 8 + g)*132 + kg0 + tg];
        u32 a2 = As[(r0 + g)*132     + kg0 + 4 + tg];
        u32 a3 = As[(r0 + 8 + g)*132 + kg0 + 4 + tg];
        #pragma unroll
        for (int ct = 0; ct < 8; ct++){
            int co = c0 + ct*8 + g;
            u32 b0 = Ws[co*132 + kg0 + tg];
            u32 b1 = Ws[co*132 + kg0 + 4 + tg];
            imma(acc[ct], a0, a1, a2, a3, b0, b1);
        }
    }
    __syncthreads();

    // ---- epilogue ----
    float mnW = g_qp[3], sW = g_qp[4];
    float SS = sA * sW;
    float c0f = 512.0f * mnA * mnW;
    float* fo = (float*)As;
    float lmin = 3.4e38f, lmax = -3.4e38f;
    #pragma unroll
    for (int hh = 0; hh < 2; hh++){
        int px = r0 + hh*8 + g;
        float t1 = __fmaf_rn(sA*mnW, (float)rs_s[px], c0f);
        #pragma unroll
        for (int ct = 0; ct < 8; ct++){
            #pragma unroll
            for (int e = 0; e < 2; e++){
                int co = c0 + ct*8 + 2*tg + e;
                float h = __fmaf_rn(SS, (float)acc[ct][hh*2+e],
                          __fmaf_rn(mnA*sW, (float)ws_s[co], t1));
                float a2v = fmaxf(__fmaf_rn(h, inv2[co], bia2[co]), 0.f);
                fo[px*132 + co] = a2v;
                lmin = fminf(lmin, a2v); lmax = fmaxf(lmax, a2v);
            }
        }
    }
    u32 emin = __reduce_min_sync(0xffffffffu, fenc(lmin));
    u32 emax = __reduce_max_sync(0xffffffffu, fenc(lmax));
    if (lane == 0){ red[wid] = emin; red[8+wid] = emax; }
    __syncthreads();
    if (tid == 0){
        u32 mn = red[0], mx = red[8];
        for (int i = 1; i < 8; i++){ mn = min(mn, red[i]); mx = max(mx, red[8+i]); }
        atomicMin(&g_mm[6], mn); atomicMax(&g_mm[7], mx);
    }
    #pragma unroll
    for (int it = 0; it < 8; it++){
        int f = it*256 + tid;
        int pxi = f >> 5, j = f & 31;
        float4 v = *(float4*)&fo[pxi*132 + j*4];
        *(float4*)&g_a2[(size_t)(p0 + pxi)*C2 + j*4] = v;
    }
}

// ---------------- K4: quantize a2 ----------------
__global__ void k_qa2(){
    int warp = threadIdx.x >> 5, lane = threadIdx.x & 31;
    int p = blockIdx.x*8 + warp;
    float mn = fdec(g_mm[6]), mx = fdec(g_mm[7]);
    float s = fmaxf(__fdiv_rn(mx - mn, 255.0f), 1e-8f), r = __frcp_rn(s);
    const float4* a4 = (const float4*)&g_a2[(size_t)p*C2];
    float4 v = a4[lane];
    int q0 = qidx(v.x, mn, s, r);
    int q1 = qidx(v.y, mn, s, r);
    int q2 = qidx(v.z, mn, s, r);
    int q3 = qidx(v.w, mn, s, r);
    g_aq2[(size_t)p*32 + lane] = (u32)q0 | ((u32)q1<<8) | ((u32)q2<<16) | ((u32)q3<<24);
    int sum = __reduce_add_sync(0xffffffffu, q0+q1+q2+q3);
    if (lane == 0) g_rs2[p] = sum;
}

// ---------------- K5: 3x3 conv via IMMA ----------------
__global__ __launch_bounds__(128) void k_conv2(float* __restrict__ out){
    __shared__ u32 Ws[32*292];      // [co][288 words], stride 292
    __shared__ u32 a_t[3*30*36];    // [row][col(halo)][32 words], stride 36
    __shared__ int   rs_s[3*30];
    __shared__ float rsum_p[28];
    __shared__ float wvL[32], wvM[32], wvR[32];

    int tid = threadIdx.x;
    int b = blockIdx.x;
    int n = b / 28, h = b % 28;
    int wid = tid >> 5, lane = tid & 31;
    int g = lane >> 2, tg = lane & 3;

    for (int f = tid; f < 9216; f += 128){
        int co = f / 288, k = f - co*288;
        Ws[co*292 + k] = g_wq2c[f];
    }
    for (int f = tid; f < 3*30*36; f += 128) a_t[f] = 0;
    if (tid < 90) rs_s[tid] = 0;
    __syncthreads();
    for (int f = tid; f < 3*28*32; f += 128){
        int rr = f / (28*32); int rem = f - rr*28*32;
        int col = rem >> 5, k = rem & 31;
        int gh = h + rr - 1;
        if ((unsigned)gh < 28u)
            a_t[(rr*30 + col + 1)*36 + k] = g_aq2[(size_t)(n*HW + gh*28 + col)*32 + k];
    }
    if (tid < 84){
        int rr = tid / 28, col = tid % 28;
        int gh = h + rr - 1;
        if ((unsigned)gh < 28u) rs_s[rr*30 + col + 1] = g_rs2[n*HW + gh*28 + col];
    }
    __syncthreads();

    if (tid < 28){
        int s = 0;
        #pragma unroll
        for (int rr = 0; rr < 3; rr++)
            #pragma unroll
            for (int dw = 0; dw < 3; dw++)
                s += rs_s[rr*30 + tid + dw];
        rsum_p[tid] = (float)s;
    }
    if (tid < 32){
        int co = tid;
        float m = 0.f, l = 0.f, r_ = 0.f;
        #pragma unroll
        for (int rr = 0; rr < 3; rr++){
            if ((unsigned)(h + rr - 1) < 28u){
                float w0 = (float)g_wts2[co*9 + rr*3 + 0];
                float w1 = (float)g_wts2[co*9 + rr*3 + 1];
                float w2 = (float)g_wts2[co*9 + rr*3 + 2];
                m  += w0 + w1 + w2;
                l  += w1 + w2;
                r_ += w0 + w1;
            }
        }
        wvM[co] = m; wvL[co] = l; wvR[co] = r_;
    }
    __syncthreads();

    int acc[2][4];
    #pragma unroll
    for (int i = 0; i < 2; i++)
        #pragma unroll
        for (int d = 0; d < 4; d++) acc[i][d] = 0;

    #pragma unroll
    for (int s = 0; s < 36; s++){
        int tap = s >> 2, chunk = s & 3;
        int rr = tap / 3, dw = tap - rr*3;
        int w0 = chunk*8 + tg;
        u32 b0 = Ws[(wid*8 + g)*292 + s*8 + tg];
        u32 b1 = Ws[(wid*8 + g)*292 + s*8 + 4 + tg];
        int rbase = rr*30 + dw;
        u32 a0 = a_t[(rbase + g)*36      + w0];
        u32 a1 = a_t[(rbase + 8 + g)*36  + w0];
        u32 a2 = a_t[(rbase + g)*36      + w0 + 4];
        u32 a3 = a_t[(rbase + 8 + g)*36  + w0 + 4];
        imma(acc[0], a0, a1, a2, a3, b0, b1);
        u32 c0 = a_t[(rbase + 16 + g)*36 + w0];
        u32 c1 = a_t[(rbase + 24 + g)*36 + w0];
        u32 c2 = a_t[(rbase + 16 + g)*36 + w0 + 4];
        u32 c3 = a_t[(rbase + 24 + g)*36 + w0 + 4];
        imma(acc[1], c0, c1, c2, c3, b0, b1);
    }

    float mnA2 = fdec(g_mm[6]), mxA2 = fdec(g_mm[7]);
    float sA2 = fmaxf(__fdiv_rn(mxA2 - mnA2, 255.0f), 1e-8f);
    float mnW = g_qp[6], sW = g_qp[7];
    float rowv = 0.f;
    #pragma unroll
    for (int rr = 0; rr < 3; rr++) rowv += ((unsigned)(h + rr - 1) < 28u) ? 1.f : 0.f;
    float SS = sA2 * sW;
    #pragma unroll
    for (int ti = 0; ti < 2; ti++){
        #pragma unroll
        for (int hh = 0; hh < 2; hh++){
            int px = ti*16 + hh*8 + g;
            if (px < 28){
                float colv = (px == 0 || px == 27) ? 2.f : 3.f;
                float nv   = rowv * colv * 128.0f;
                float rp   = rsum_p[px];
                #pragma unroll
                for (int e = 0; e < 2; e++){
                    int co = wid*8 + 2*tg + e;
                    float wvv = (px == 0) ? wvL[co] : ((px == 27) ? wvR[co] : wvM[co]);
                    float o = __fmaf_rn(SS, (float)acc[ti][hh*2+e],
                              __fmaf_rn(sA2*mnW, rp,
                              __fmaf_rn(mnA2*sW, wvv, mnA2*mnW*nv)));
                    out[((size_t)n*32 + co)*HW + h*28 + px] = o;
                }
            }
        }
    }
}

extern "C" void kernel_launch(void* const* d_in, const int* in_sizes, int n_in,
                              void* d_out, int out_size){
    const float* x  = (const float*)d_in[0];
    const float* g1 = (const float*)d_in[1];
    const float* b1 = (const float*)d_in[2];
    const float* m1 = (const float*)d_in[3];
    const float* v1 = (const float*)d_in[4];
    const float* w1 = (const float*)d_in[5];
    const float* g2 = (const float*)d_in[6];
    const float* b2 = (const float*)d_in[7];
    const float* m2 = (const float*)d_in[8];
    const float* v2 = (const float*)d_in[9];
    const float* w2 = (const float*)d_in[10];
    float* out = (float*)d_out;

    cudaFuncSetAttribute(k_conv1, cudaFuncAttributeMaxDynamicSharedMemorySize, DYN_SMEM);

    k_mm   <<<2064, 256>>>(x, w1, w2);
    k_prep <<<161, 256>>>(w1, w2, g1, b1, m1, v1);
    k_conv1<<<784, 256, DYN_SMEM>>>(x, g1, b1, m1, v1, g2, b2, m2, v2);
    k_qa2  <<<6272, 256>>>();
    k_conv2<<<1792, 128>>>(out);
}

// round 8
// speedup vs baseline: 1.3533x; 1.1494x over previous
#include <cuda_runtime.h>
#include <cstdint>

typedef unsigned int u32;

#define EPSBN 1e-5f
#define C1 512
#define C2 128
#define C3 32
#define HW 784
#define PTOT (64*HW)     // 50176

// ---------------- device scratch ----------------
__device__ float g_cmn[C1], g_cmx[C1];       // per-channel raw x min/max
__device__ u32   g_wpmn[16], g_wpmx[16];     // w1 (0..7) / w2 (8..15) encoded partials
__device__ u32   g_mm[8];                    // [6,7] = a2 min/max atomics
__device__ float g_qp[12];                   // [0..2]=a1 [3..5]=w1 [6..8]=w2  (mn,s,rcp)
__device__ u32   g_wq1_32[C2*C1/4];          // w1 u8 packed [co][128]
__device__ int   g_ws1[C2];                  // per-co w1 index sums
__device__ u32   g_wq2c[C3*288];             // w2 u8 packed [co][tap*32+kg]  (co-major)
__device__ int   g_wts2[C3*9];               // per-(co,tap) w2 index sums
__device__ float g_a2[(size_t)PTOT*C2];      // relu(bn2(h)) fp32 NHWC (25.7MB)
__device__ u32   g_aq2[(size_t)PTOT*32];     // quantized a2 u8x4 NHWC (6.4MB)
__device__ int   g_rs2[PTOT];                // per-pixel a2 index sums

// ---------------- helpers ----------------
__device__ __forceinline__ u32 fenc(float f){
    u32 u = __float_as_uint(f);
    return (u & 0x80000000u) ? ~u : (u | 0x80000000u);
}
__device__ __forceinline__ float fdec(u32 e){
    return __uint_as_float((e & 0x80000000u) ? (e & 0x7fffffffu) : ~e);
}
__device__ __forceinline__ int qidx(float v, float mn, float s, float r){
    float t  = __fsub_rn(v, mn);
    float q0 = __fmul_rn(t, r);
    float q  = __fmaf_rn(__fmaf_rn(-s, q0, t), r, q0);
    int i = __float2int_rn(q);
    i = i < 0 ? 0 : i;
    return i > 255 ? 255 : i;
}
// u8 IMMA: D(16x8,s32) += A(16x32,u8,row) * B(32x8,u8,col)
__device__ __forceinline__ void imma(int* c, u32 a0, u32 a1, u32 a2, u32 a3, u32 b0, u32 b1){
    asm volatile("mma.sync.aligned.m16n8k32.row.col.s32.u8.u8.s32 "
                 "{%0,%1,%2,%3},{%4,%5,%6,%7},{%8,%9},{%0,%1,%2,%3};"
                 : "+r"(c[0]), "+r"(c[1]), "+r"(c[2]), "+r"(c[3])
                 : "r"(a0), "r"(a1), "r"(a2), "r"(a3), "r"(b0), "r"(b1));
}

// ---------------- K1: raw min/max ----------------
// b < 512: channel b — min/max of x[:, b, :, :] (64 planes x 196 float4)
// b in [512,520): w1 chunk;  b in [520,528): w2 chunk
__global__ __launch_bounds__(256) void k_mm(const float* __restrict__ x,
                     const float* __restrict__ w1, const float* __restrict__ w2){
    __shared__ float rmn[8], rmx[8];
    __shared__ u32 wmin[8], wmax[8];
    int b = blockIdx.x, t = threadIdx.x;
    if (b < 512){
        const float4* x4 = (const float4*)x;
        float mn = 3.4e38f, mx = -3.4e38f;
        if (t < 196){
            #pragma unroll 1
            for (int n0 = 0; n0 < 64; n0 += 4){
                float4 v0 = x4[((size_t)(n0+0)*C1 + b)*196 + t];
                float4 v1 = x4[((size_t)(n0+1)*C1 + b)*196 + t];
                float4 v2 = x4[((size_t)(n0+2)*C1 + b)*196 + t];
                float4 v3 = x4[((size_t)(n0+3)*C1 + b)*196 + t];
                float lo0 = fminf(fminf(v0.x, v0.y), fminf(v0.z, v0.w));
                float hi0 = fmaxf(fmaxf(v0.x, v0.y), fmaxf(v0.z, v0.w));
                float lo1 = fminf(fminf(v1.x, v1.y), fminf(v1.z, v1.w));
                float hi1 = fmaxf(fmaxf(v1.x, v1.y), fmaxf(v1.z, v1.w));
                float lo2 = fminf(fminf(v2.x, v2.y), fminf(v2.z, v2.w));
                float hi2 = fmaxf(fmaxf(v2.x, v2.y), fmaxf(v2.z, v2.w));
                float lo3 = fminf(fminf(v3.x, v3.y), fminf(v3.z, v3.w));
                float hi3 = fmaxf(fmaxf(v3.x, v3.y), fmaxf(v3.z, v3.w));
                mn = fminf(mn, fminf(fminf(lo0, lo1), fminf(lo2, lo3)));
                mx = fmaxf(mx, fmaxf(fmaxf(hi0, hi1), fmaxf(hi2, hi3)));
            }
        }
        #pragma unroll
        for (int off = 16; off; off >>= 1){
            mn = fminf(mn, __shfl_xor_sync(0xffffffffu, mn, off));
            mx = fmaxf(mx, __shfl_xor_sync(0xffffffffu, mx, off));
        }
        if ((t & 31) == 0){ rmn[t>>5] = mn; rmx[t>>5] = mx; }
        __syncthreads();
        if (t == 0){
            for (int i = 1; i < 8; i++){ mn = fminf(mn, rmn[i]); mx = fmaxf(mx, rmx[i]); }
            g_cmn[b] = mn; g_cmx[b] = mx;
        }
    } else {
        float lmin = 3.4e38f, lmax = -3.4e38f;
        int slot;
        if (b < 520){
            slot = b - 512;
            int s0 = slot*8192;
            for (int i = t; i < 8192; i += 256){
                float v = w1[s0+i];
                lmin = fminf(lmin, v); lmax = fmaxf(lmax, v);
            }
        } else {
            slot = 8 + (b - 520);
            int s0 = (b-520)*4608;
            for (int i = t; i < 4608; i += 256){
                float v = w2[s0+i];
                lmin = fminf(lmin, v); lmax = fmaxf(lmax, v);
            }
        }
        u32 emin = __reduce_min_sync(0xffffffffu, fenc(lmin));
        u32 emax = __reduce_max_sync(0xffffffffu, fenc(lmax));
        if ((t & 31) == 0){ wmin[t>>5] = emin; wmax[t>>5] = emax; }
        __syncthreads();
        if (t == 0){
            u32 mn = wmin[0], mx = wmax[0];
            for (int i = 1; i < 8; i++){ mn = min(mn, wmin[i]); mx = max(mx, wmax[i]); }
            g_wpmn[slot] = mn; g_wpmx[slot] = mx;
        }
    }
}

// ---------------- K2: params + weight quantization ----------------
__global__ void k_prep(const float* __restrict__ w1, const float* __restrict__ w2,
                       const float* __restrict__ g1, const float* __restrict__ b1,
                       const float* __restrict__ m1, const float* __restrict__ v1){
    __shared__ int ss[9];
    __shared__ float red[64];
    int b = blockIdx.x, t = threadIdx.x;
    if (b < 128){
        u32 emn = g_wpmn[0], emx = g_wpmx[0];
        #pragma unroll
        for (int i = 1; i < 8; i++){ emn = min(emn, g_wpmn[i]); emx = max(emx, g_wpmx[i]); }
        float mn = fdec(emn), mx = fdec(emx);
        float s = fmaxf(__fdiv_rn(mx - mn, 255.0f), 1e-8f), r = __frcp_rn(s);
        int co = b;
        int lsum = 0;
        if (t < 128){
            u32 pack = 0;
            #pragma unroll
            for (int j = 0; j < 4; j++){
                int q = qidx(w1[co*C1 + 4*t + j], mn, s, r);
                pack |= (u32)q << (8*j);
                lsum += q;
            }
            g_wq1_32[co*128 + t] = pack;
        }
        lsum = __reduce_add_sync(0xffffffffu, lsum);
        if ((t & 31) == 0) ss[t>>5] = lsum;
        __syncthreads();
        if (t == 0){
            g_ws1[co] = ss[0] + ss[1] + ss[2] + ss[3];
            if (co == 0){ g_qp[3]=mn; g_qp[4]=s; g_qp[5]=r; }
        }
    } else if (b < 160){
        int co = b - 128;
        u32 emn = g_wpmn[8], emx = g_wpmx[8];
        #pragma unroll
        for (int i = 1; i < 8; i++){ emn = min(emn, g_wpmn[8+i]); emx = max(emx, g_wpmx[8+i]); }
        float mn = fdec(emn), mx = fdec(emx);
        float s = fmaxf(__fdiv_rn(mx - mn, 255.0f), 1e-8f), r = __frcp_rn(s);
        if (t < 9) ss[t] = 0;
        __syncthreads();
        for (int f = t; f < 288; f += 256){
            int tap = f >> 5, kg = f & 31;
            u32 pack = 0; int psum = 0;
            #pragma unroll
            for (int j = 0; j < 4; j++){
                int ci = kg*4 + j;
                int q = qidx(w2[co*1152 + ci*9 + tap], mn, s, r);
                pack |= (u32)q << (8*j);
                psum += q;
            }
            g_wq2c[co*288 + f] = pack;
            atomicAdd(&ss[tap], psum);
        }
        __syncthreads();
        if (t < 9) g_wts2[co*9 + t] = ss[t];
        if (t == 0 && co == 0){ g_qp[6]=mn; g_qp[7]=s; g_qp[8]=r; }
    } else {
        // a1 params: monotone bn1+relu transform on 512 per-channel extremes
        float gmn = 3.4e38f, gmx = -3.4e38f;
        for (int c = t; c < C1; c += 256){
            float iv = __fdiv_rn(g1[c], __fsqrt_rn(v1[c] + EPSBN));
            float bb = __fmaf_rn(-m1[c], iv, b1[c]);
            float v0 = __fmaf_rn(iv, g_cmn[c], bb);
            float v1_ = __fmaf_rn(iv, g_cmx[c], bb);
            float lo = fmaxf(fminf(v0, v1_), 0.f);
            float hi = fmaxf(fmaxf(v0, v1_), 0.f);
            gmn = fminf(gmn, lo);
            gmx = fmaxf(gmx, hi);
        }
        #pragma unroll
        for (int off = 16; off; off >>= 1){
            gmn = fminf(gmn, __shfl_xor_sync(0xffffffffu, gmn, off));
            gmx = fmaxf(gmx, __shfl_xor_sync(0xffffffffu, gmx, off));
        }
        if ((t & 31) == 0){ red[t>>5] = gmn; red[32 + (t>>5)] = gmx; }
        __syncthreads();
        if (t == 0){
            float mn = red[0], mx = red[32];
            for (int i = 1; i < 8; i++){ mn = fminf(mn, red[i]); mx = fmaxf(mx, red[32+i]); }
            float s = fmaxf(__fdiv_rn(mx - mn, 255.0f), 1e-8f);
            g_qp[0] = mn; g_qp[1] = s; g_qp[2] = __frcp_rn(s);
            g_mm[6] = 0xFFFFFFFFu; g_mm[7] = 0u;
        }
    }
}

// ---------------- K3: conv1 via IMMA, 64px tiles, 2 CTA/SM ----------------
#define AS_U32   (64*132)         // 8448
#define WS_U32   (128*132)        // 16896
#define SP_U32   (AS_U32+WS_U32)  // 25344
#define DYN_SMEM (SP_U32*4 + 6400)

__global__ __launch_bounds__(256,2) void k_conv1(
    const float* __restrict__ x,
    const float* __restrict__ g1, const float* __restrict__ b1,
    const float* __restrict__ m1, const float* __restrict__ v1,
    const float* __restrict__ g2, const float* __restrict__ b2,
    const float* __restrict__ m2, const float* __restrict__ v2)
{
    extern __shared__ __align__(16) u32 sm[];
    u32* As = sm;
    u32* Ws = sm + AS_U32;
    float* inv1 = (float*)(sm + SP_U32);
    float* bia1 = inv1 + 512;
    float* inv2 = bia1 + 512;
    float* bia2 = inv2 + 128;
    int*   ws_s = (int*)(bia2 + 128);
    int*   rs_s = ws_s + 128;
    u32*   red  = (u32*)(rs_s + 64);

    int tid = threadIdx.x, wid = tid >> 5, lane = tid & 31;
    int g = lane >> 2, tg = lane & 3;
    int p0 = blockIdx.x * 64;

    for (int c = tid; c < C1; c += 256){
        float iv = __fdiv_rn(g1[c], __fsqrt_rn(v1[c] + EPSBN));
        inv1[c] = iv; bia1[c] = __fmaf_rn(-m1[c], iv, b1[c]);
    }
    if (tid < 128){
        float iv = __fdiv_rn(g2[tid], __fsqrt_rn(v2[tid] + EPSBN));
        inv2[tid] = iv; bia2[tid] = __fmaf_rn(-m2[tid], iv, b2[tid]);
        ws_s[tid] = g_ws1[tid];
    }
    if (tid < 64) rs_s[tid] = 0;
    #pragma unroll
    for (int it = 0; it < 64; it++){
        int f = it*256 + tid;
        Ws[(f>>7)*132 + (f&127)] = g_wq1_32[f];
    }
    __syncthreads();

    float mnA = g_qp[0], sA = g_qp[1], rA = g_qp[2];

    // ---- build quantized u8 activation tile A [64px][512ci] ----
    {
        int px = tid & 63, q4 = tid >> 6;
        int p = p0 + px;
        u32 base = (u32)((p/HW)*(C1*HW) + (p%HW));
        int ci0 = q4 * 128;
        int lsum = 0;
        #pragma unroll 4
        for (int m = 0; m < 32; m++){
            int ci = ci0 + 4*m;
            u32 pack = 0;
            #pragma unroll
            for (int j = 0; j < 4; j++){
                float xv = x[base + (u32)(ci+j)*HW];
                float a = fmaxf(__fmaf_rn(xv, inv1[ci+j], bia1[ci+j]), 0.f);
                int q = qidx(a, mnA, sA, rA);
                pack |= (u32)q << (8*j);
                lsum += q;
            }
            As[px*132 + q4*32 + m] = pack;
        }
        atomicAdd(&rs_s[px], lsum);
    }
    __syncthreads();

    // ---- IMMA mainloop: warp computes 16px x 64co ----
    int r0 = (wid >> 1) * 16;
    int c0 = (wid & 1) * 64;
    int acc[8][4];
    #pragma unroll
    for (int ct = 0; ct < 8; ct++)
        #pragma unroll
        for (int d = 0; d < 4; d++) acc[ct][d] = 0;

    #pragma unroll 4
    for (int kk = 0; kk < 16; kk++){
        int kg0 = kk*8;
        u32 a0 = As[(r0 + g)*132     + kg0 + tg];
        u32 a1 = As[(r0 + 8 + g)*132 + kg0 + tg];
        u32 a2 = As[(r0 + g)*132     + kg0 + 4 + tg];
        u32 a3 = As[(r0 + 8 + g)*132 + kg0 + 4 + tg];
        #pragma unroll
        for (int ct = 0; ct < 8; ct++){
            int co = c0 + ct*8 + g;
            u32 b0 = Ws[co*132 + kg0 + tg];
            u32 b1 = Ws[co*132 + kg0 + 4 + tg];
            imma(acc[ct], a0, a1, a2, a3, b0, b1);
        }
    }
    __syncthreads();

    // ---- epilogue ----
    float mnW = g_qp[3], sW = g_qp[4];
    float SS = sA * sW;
    float c0f = 512.0f * mnA * mnW;
    float* fo = (float*)As;
    float lmin = 3.4e38f, lmax = -3.4e38f;
    #pragma unroll
    for (int hh = 0; hh < 2; hh++){
        int px = r0 + hh*8 + g;
        float t1 = __fmaf_rn(sA*mnW, (float)rs_s[px], c0f);
        #pragma unroll
        for (int ct = 0; ct < 8; ct++){
            #pragma unroll
            for (int e = 0; e < 2; e++){
                int co = c0 + ct*8 + 2*tg + e;
                float h = __fmaf_rn(SS, (float)acc[ct][hh*2+e],
                          __fmaf_rn(mnA*sW, (float)ws_s[co], t1));
                float a2v = fmaxf(__fmaf_rn(h, inv2[co], bia2[co]), 0.f);
                fo[px*132 + co] = a2v;
                lmin = fminf(lmin, a2v); lmax = fmaxf(lmax, a2v);
            }
        }
    }
    u32 emin = __reduce_min_sync(0xffffffffu, fenc(lmin));
    u32 emax = __reduce_max_sync(0xffffffffu, fenc(lmax));
    if (lane == 0){ red[wid] = emin; red[8+wid] = emax; }
    __syncthreads();
    if (tid == 0){
        u32 mn = red[0], mx = red[8];
        for (int i = 1; i < 8; i++){ mn = min(mn, red[i]); mx = max(mx, red[8+i]); }
        atomicMin(&g_mm[6], mn); atomicMax(&g_mm[7], mx);
    }
    #pragma unroll
    for (int it = 0; it < 8; it++){
        int f = it*256 + tid;
        int pxi = f >> 5, j = f & 31;
        float4 v = *(float4*)&fo[pxi*132 + j*4];
        *(float4*)&g_a2[(size_t)(p0 + pxi)*C2 + j*4] = v;
    }
}

// ---------------- K4: quantize a2 ----------------
__global__ void k_qa2(){
    int warp = threadIdx.x >> 5, lane = threadIdx.x & 31;
    int p = blockIdx.x*8 + warp;
    float mn = fdec(g_mm[6]), mx = fdec(g_mm[7]);
    float s = fmaxf(__fdiv_rn(mx - mn, 255.0f), 1e-8f), r = __frcp_rn(s);
    const float4* a4 = (const float4*)&g_a2[(size_t)p*C2];
    float4 v = a4[lane];
    int q0 = qidx(v.x, mn, s, r);
    int q1 = qidx(v.y, mn, s, r);
    int q2 = qidx(v.z, mn, s, r);
    int q3 = qidx(v.w, mn, s, r);
    g_aq2[(size_t)p*32 + lane] = (u32)q0 | ((u32)q1<<8) | ((u32)q2<<16) | ((u32)q3<<24);
    int sum = __reduce_add_sync(0xffffffffu, q0+q1+q2+q3);
    if (lane == 0) g_rs2[p] = sum;
}

// ---------------- K5: 3x3 conv via IMMA ----------------
__global__ __launch_bounds__(128) void k_conv2(float* __restrict__ out){
    __shared__ u32 Ws[32*292];      // [co][288 words], stride 292
    __shared__ u32 a_t[3*30*36];    // [row][col(halo)][32 words], stride 36
    __shared__ int   rs_s[3*30];
    __shared__ float rsum_p[28];
    __shared__ float wvL[32], wvM[32], wvR[32];

    int tid = threadIdx.x;
    int b = blockIdx.x;
    int n = b / 28, h = b % 28;
    int wid = tid >> 5, lane = tid & 31;
    int g = lane >> 2, tg = lane & 3;

    for (int f = tid; f < 9216; f += 128){
        int co = f / 288, k = f - co*288;
        Ws[co*292 + k] = g_wq2c[f];
    }
    for (int f = tid; f < 3*30*36; f += 128) a_t[f] = 0;
    if (tid < 90) rs_s[tid] = 0;
    __syncthreads();
    for (int f = tid; f < 3*28*32; f += 128){
        int rr = f / (28*32); int rem = f - rr*28*32;
        int col = rem >> 5, k = rem & 31;
        int gh = h + rr - 1;
        if ((unsigned)gh < 28u)
            a_t[(rr*30 + col + 1)*36 + k] = g_aq2[(size_t)(n*HW + gh*28 + col)*32 + k];
    }
    if (tid < 84){
        int rr = tid / 28, col = tid % 28;
        int gh = h + rr - 1;
        if ((unsigned)gh < 28u) rs_s[rr*30 + col + 1] = g_rs2[n*HW + gh*28 + col];
    }
    __syncthreads();

    if (tid < 28){
        int s = 0;
        #pragma unroll
        for (int rr = 0; rr < 3; rr++)
            #pragma unroll
            for (int dw = 0; dw < 3; dw++)
                s += rs_s[rr*30 + tid + dw];
        rsum_p[tid] = (float)s;
    }
    if (tid < 32){
        int co = tid;
        float m = 0.f, l = 0.f, r_ = 0.f;
        #pragma unroll
        for (int rr = 0; rr < 3; rr++){
            if ((unsigned)(h + rr - 1) < 28u){
                float w0 = (float)g_wts2[co*9 + rr*3 + 0];
                float w1 = (float)g_wts2[co*9 + rr*3 + 1];
                float w2 = (float)g_wts2[co*9 + rr*3 + 2];
                m  += w0 + w1 + w2;
                l  += w1 + w2;
                r_ += w0 + w1;
            }
        }
        wvM[co] = m; wvL[co] = l; wvR[co] = r_;
    }
    __syncthreads();

    int acc[2][4];
    #pragma unroll
    for (int i = 0; i < 2; i++)
        #pragma unroll
        for (int d = 0; d < 4; d++) acc[i][d] = 0;

    #pragma unroll
    for (int s = 0; s < 36; s++){
        int tap = s >> 2, chunk = s & 3;
        int rr = tap / 3, dw = tap - rr*3;
        int w0 = chunk*8 + tg;
        u32 b0 = Ws[(wid*8 + g)*292 + s*8 + tg];
        u32 b1 = Ws[(wid*8 + g)*292 + s*8 + 4 + tg];
        int rbase = rr*30 + dw;
        u32 a0 = a_t[(rbase + g)*36      + w0];
        u32 a1 = a_t[(rbase + 8 + g)*36  + w0];
        u32 a2 = a_t[(rbase + g)*36      + w0 + 4];
        u32 a3 = a_t[(rbase + 8 + g)*36  + w0 + 4];
        imma(acc[0], a0, a1, a2, a3, b0, b1);
        u32 c0 = a_t[(rbase + 16 + g)*36 + w0];
        u32 c1 = a_t[(rbase + 24 + g)*36 + w0];
        u32 c2 = a_t[(rbase + 16 + g)*36 + w0 + 4];
        u32 c3 = a_t[(rbase + 24 + g)*36 + w0 + 4];
        imma(acc[1], c0, c1, c2, c3, b0, b1);
    }

    float mnA2 = fdec(g_mm[6]), mxA2 = fdec(g_mm[7]);
    float sA2 = fmaxf(__fdiv_rn(mxA2 - mnA2, 255.0f), 1e-8f);
    float mnW = g_qp[6], sW = g_qp[7];
    float rowv = 0.f;
    #pragma unroll
    for (int rr = 0; rr < 3; rr++) rowv += ((unsigned)(h + rr - 1) < 28u) ? 1.f : 0.f;
    float SS = sA2 * sW;
    #pragma unroll
    for (int ti = 0; ti < 2; ti++){
        #pragma unroll
        for (int hh = 0; hh < 2; hh++){
            int px = ti*16 + hh*8 + g;
            if (px < 28){
                float colv = (px == 0 || px == 27) ? 2.f : 3.f;
                float nv   = rowv * colv * 128.0f;
                float rp   = rsum_p[px];
                #pragma unroll
                for (int e = 0; e < 2; e++){
                    int co = wid*8 + 2*tg + e;
                    float wvv = (px == 0) ? wvL[co] : ((px == 27) ? wvR[co] : wvM[co]);
                    float o = __fmaf_rn(SS, (float)acc[ti][hh*2+e],
                              __fmaf_rn(sA2*mnW, rp,
                              __fmaf_rn(mnA2*sW, wvv, mnA2*mnW*nv)));
                    out[((size_t)n*32 + co)*HW + h*28 + px] = o;
                }
            }
        }
    }
}

extern "C" void kernel_launch(void* const* d_in, const int* in_sizes, int n_in,
                              void* d_out, int out_size){
    const float* x  = (const float*)d_in[0];
    const float* g1 = (const float*)d_in[1];
    const float* b1 = (const float*)d_in[2];
    const float* m1 = (const float*)d_in[3];
    const float* v1 = (const float*)d_in[4];
    const float* w1 = (const float*)d_in[5];
    const float* g2 = (const float*)d_in[6];
    const float* b2 = (const float*)d_in[7];
    const float* m2 = (const float*)d_in[8];
    const float* v2 = (const float*)d_in[9];
    const float* w2 = (const float*)d_in[10];
    float* out = (float*)d_out;

    cudaFuncSetAttribute(k_conv1, cudaFuncAttributeMaxDynamicSharedMemorySize, DYN_SMEM);

    k_mm   <<<528, 256>>>(x, w1, w2);
    k_prep <<<161, 256>>>(w1, w2, g1, b1, m1, v1);
    k_conv1<<<784, 256, DYN_SMEM>>>(x, g1, b1, m1, v1, g2, b2, m2, v2);
    k_qa2  <<<6272, 256>>>();
    k_conv2<<<1792, 128>>>(out);
}

// round 9
// speedup vs baseline: 1.3966x; 1.0321x over previous
#include <cuda_runtime.h>
#include <cstdint>

typedef unsigned int u32;

#define EPSBN 1e-5f
#define C1 512
#define C2 128
#define C3 32
#define HW 784
#define PTOT (64*HW)     // 50176

// ---------------- device scratch ----------------
__device__ float g_cmn[C1], g_cmx[C1];       // per-channel raw x min/max
__device__ u32   g_wpmn[16], g_wpmx[16];     // w1 (0..7) / w2 (8..15) encoded partials
__device__ u32   g_mm[8];                    // [6,7] = a2 min/max atomics
__device__ float g_qp[12];                   // [0..2]=a1 [3..5]=w1 [6..8]=w2  (mn,s,rcp)
__device__ u32   g_wq1_32[C2*C1/4];          // w1 u8 packed [co][128]
__device__ int   g_ws1[C2];                  // per-co w1 index sums
__device__ u32   g_wq2c[C3*288];             // w2 u8 packed [co][tap*32+kg]  (co-major)
__device__ int   g_wts2[C3*9];               // per-(co,tap) w2 index sums
__device__ float g_a2[(size_t)PTOT*C2];      // relu(bn2(h)) fp32 NHWC (25.7MB)
__device__ u32   g_aq2[(size_t)PTOT*32];     // quantized a2 u8x4 NHWC (6.4MB)
__device__ int   g_rs2[PTOT];                // per-pixel a2 index sums

// ---------------- helpers ----------------
__device__ __forceinline__ u32 fenc(float f){
    u32 u = __float_as_uint(f);
    return (u & 0x80000000u) ? ~u : (u | 0x80000000u);
}
__device__ __forceinline__ float fdec(u32 e){
    return __uint_as_float((e & 0x80000000u) ? (e & 0x7fffffffu) : ~e);
}
__device__ __forceinline__ int qidx(float v, float mn, float s, float r){
    float t  = __fsub_rn(v, mn);
    float q0 = __fmul_rn(t, r);
    float q  = __fmaf_rn(__fmaf_rn(-s, q0, t), r, q0);
    int i = __float2int_rn(q);
    i = i < 0 ? 0 : i;
    return i > 255 ? 255 : i;
}
// u8 IMMA: D(16x8,s32) += A(16x32,u8,row) * B(32x8,u8,col)
__device__ __forceinline__ void imma(int* c, u32 a0, u32 a1, u32 a2, u32 a3, u32 b0, u32 b1){
    asm volatile("mma.sync.aligned.m16n8k32.row.col.s32.u8.u8.s32 "
                 "{%0,%1,%2,%3},{%4,%5,%6,%7},{%8,%9},{%0,%1,%2,%3};"
                 : "+r"(c[0]), "+r"(c[1]), "+r"(c[2]), "+r"(c[3])
                 : "r"(a0), "r"(a1), "r"(a2), "r"(a3), "r"(b0), "r"(b1));
}

// ---------------- K1: raw min/max ----------------
// b < 512: channel b — min/max of x[:, b, :, :] (64 planes x 196 float4)
// b in [512,520): w1 chunk;  b in [520,528): w2 chunk
__global__ __launch_bounds__(256) void k_mm(const float* __restrict__ x,
                     const float* __restrict__ w1, const float* __restrict__ w2){
    __shared__ float rmn[8], rmx[8];
    __shared__ u32 wmin[8], wmax[8];
    int b = blockIdx.x, t = threadIdx.x;
    if (b < 512){
        const float4* x4 = (const float4*)x;
        float mn = 3.4e38f, mx = -3.4e38f;
        // 64 planes x 196 float4 = 12544 items, 256 threads x 49 iters, all independent
        #pragma unroll 7
        for (int k = 0; k < 49; k++){
            int i = t + k*256;
            int n = i / 196, rr = i - n*196;
            float4 v = x4[((size_t)n*C1 + b)*196 + rr];
            mn = fminf(mn, fminf(fminf(v.x, v.y), fminf(v.z, v.w)));
            mx = fmaxf(mx, fmaxf(fmaxf(v.x, v.y), fmaxf(v.z, v.w)));
        }
        #pragma unroll
        for (int off = 16; off; off >>= 1){
            mn = fminf(mn, __shfl_xor_sync(0xffffffffu, mn, off));
            mx = fmaxf(mx, __shfl_xor_sync(0xffffffffu, mx, off));
        }
        if ((t & 31) == 0){ rmn[t>>5] = mn; rmx[t>>5] = mx; }
        __syncthreads();
        if (t == 0){
            for (int i = 1; i < 8; i++){ mn = fminf(mn, rmn[i]); mx = fmaxf(mx, rmx[i]); }
            g_cmn[b] = mn; g_cmx[b] = mx;
        }
    } else {
        float lmin = 3.4e38f, lmax = -3.4e38f;
        int slot;
        if (b < 520){
            slot = b - 512;
            int s0 = slot*8192;
            for (int i = t; i < 8192; i += 256){
                float v = w1[s0+i];
                lmin = fminf(lmin, v); lmax = fmaxf(lmax, v);
            }
        } else {
            slot = 8 + (b - 520);
            int s0 = (b-520)*4608;
            for (int i = t; i < 4608; i += 256){
                float v = w2[s0+i];
                lmin = fminf(lmin, v); lmax = fmaxf(lmax, v);
            }
        }
        u32 emin = __reduce_min_sync(0xffffffffu, fenc(lmin));
        u32 emax = __reduce_max_sync(0xffffffffu, fenc(lmax));
        if ((t & 31) == 0){ wmin[t>>5] = emin; wmax[t>>5] = emax; }
        __syncthreads();
        if (t == 0){
            u32 mn = wmin[0], mx = wmax[0];
            for (int i = 1; i < 8; i++){ mn = min(mn, wmin[i]); mx = max(mx, wmax[i]); }
            g_wpmn[slot] = mn; g_wpmx[slot] = mx;
        }
    }
}

// ---------------- K2: params + weight quantization ----------------
__global__ void k_prep(const float* __restrict__ w1, const float* __restrict__ w2,
                       const float* __restrict__ g1, const float* __restrict__ b1,
                       const float* __restrict__ m1, const float* __restrict__ v1){
    __shared__ int ss[9];
    __shared__ float red[64];
    int b = blockIdx.x, t = threadIdx.x;
    if (b < 128){
        u32 emn = g_wpmn[0], emx = g_wpmx[0];
        #pragma unroll
        for (int i = 1; i < 8; i++){ emn = min(emn, g_wpmn[i]); emx = max(emx, g_wpmx[i]); }
        float mn = fdec(emn), mx = fdec(emx);
        float s = fmaxf(__fdiv_rn(mx - mn, 255.0f), 1e-8f), r = __frcp_rn(s);
        int co = b;
        int lsum = 0;
        if (t < 128){
            u32 pack = 0;
            #pragma unroll
            for (int j = 0; j < 4; j++){
                int q = qidx(w1[co*C1 + 4*t + j], mn, s, r);
                pack |= (u32)q << (8*j);
                lsum += q;
            }
            g_wq1_32[co*128 + t] = pack;
        }
        lsum = __reduce_add_sync(0xffffffffu, lsum);
        if ((t & 31) == 0) ss[t>>5] = lsum;
        __syncthreads();
        if (t == 0){
            g_ws1[co] = ss[0] + ss[1] + ss[2] + ss[3];
            if (co == 0){ g_qp[3]=mn; g_qp[4]=s; g_qp[5]=r; }
        }
    } else if (b < 160){
        int co = b - 128;
        u32 emn = g_wpmn[8], emx = g_wpmx[8];
        #pragma unroll
        for (int i = 1; i < 8; i++){ emn = min(emn, g_wpmn[8+i]); emx = max(emx, g_wpmx[8+i]); }
        float mn = fdec(emn), mx = fdec(emx);
        float s = fmaxf(__fdiv_rn(mx - mn, 255.0f), 1e-8f), r = __frcp_rn(s);
        if (t < 9) ss[t] = 0;
        __syncthreads();
        for (int f = t; f < 288; f += 256){
            int tap = f >> 5, kg = f & 31;
            u32 pack = 0; int psum = 0;
            #pragma unroll
            for (int j = 0; j < 4; j++){
                int ci = kg*4 + j;
                int q = qidx(w2[co*1152 + ci*9 + tap], mn, s, r);
                pack |= (u32)q << (8*j);
                psum += q;
            }
            g_wq2c[co*288 + f] = pack;
            atomicAdd(&ss[tap], psum);
        }
        __syncthreads();
        if (t < 9) g_wts2[co*9 + t] = ss[t];
        if (t == 0 && co == 0){ g_qp[6]=mn; g_qp[7]=s; g_qp[8]=r; }
    } else {
        // a1 params: monotone bn1+relu transform on 512 per-channel extremes
        float gmn = 3.4e38f, gmx = -3.4e38f;
        for (int c = t; c < C1; c += 256){
            float iv = __fdiv_rn(g1[c], __fsqrt_rn(v1[c] + EPSBN));
            float bb = __fmaf_rn(-m1[c], iv, b1[c]);
            float v0 = __fmaf_rn(iv, g_cmn[c], bb);
            float v1_ = __fmaf_rn(iv, g_cmx[c], bb);
            float lo = fmaxf(fminf(v0, v1_), 0.f);
            float hi = fmaxf(fmaxf(v0, v1_), 0.f);
            gmn = fminf(gmn, lo);
            gmx = fmaxf(gmx, hi);
        }
        #pragma unroll
        for (int off = 16; off; off >>= 1){
            gmn = fminf(gmn, __shfl_xor_sync(0xffffffffu, gmn, off));
            gmx = fmaxf(gmx, __shfl_xor_sync(0xffffffffu, gmx, off));
        }
        if ((t & 31) == 0){ red[t>>5] = gmn; red[32 + (t>>5)] = gmx; }
        __syncthreads();
        if (t == 0){
            float mn = red[0], mx = red[32];
            for (int i = 1; i < 8; i++){ mn = fminf(mn, red[i]); mx = fmaxf(mx, red[32+i]); }
            float s = fmaxf(__fdiv_rn(mx - mn, 255.0f), 1e-8f);
            g_qp[0] = mn; g_qp[1] = s; g_qp[2] = __frcp_rn(s);
            g_mm[6] = 0xFFFFFFFFu; g_mm[7] = 0u;
        }
    }
}

// ---------------- K3: conv1 via IMMA, 64px tiles, 2 CTA/SM ----------------
#define AS_U32   (64*132)         // 8448
#define WS_U32   (128*132)        // 16896
#define SP_U32   (AS_U32+WS_U32)  // 25344
#define DYN_SMEM (SP_U32*4 + 6400)

__global__ __launch_bounds__(256,2) void k_conv1(
    const float* __restrict__ x,
    const float* __restrict__ g1, const float* __restrict__ b1,
    const float* __restrict__ m1, const float* __restrict__ v1,
    const float* __restrict__ g2, const float* __restrict__ b2,
    const float* __restrict__ m2, const float* __restrict__ v2)
{
    extern __shared__ __align__(16) u32 sm[];
    u32* As = sm;
    u32* Ws = sm + AS_U32;
    float* inv1 = (float*)(sm + SP_U32);
    float* bia1 = inv1 + 512;
    float* inv2 = bia1 + 512;
    float* bia2 = inv2 + 128;
    int*   ws_s = (int*)(bia2 + 128);
    int*   rs_s = ws_s + 128;
    u32*   red  = (u32*)(rs_s + 64);

    int tid = threadIdx.x, wid = tid >> 5, lane = tid & 31;
    int g = lane >> 2, tg = lane & 3;
    int p0 = blockIdx.x * 64;

    for (int c = tid; c < C1; c += 256){
        float iv = __fdiv_rn(g1[c], __fsqrt_rn(v1[c] + EPSBN));
        inv1[c] = iv; bia1[c] = __fmaf_rn(-m1[c], iv, b1[c]);
    }
    if (tid < 128){
        float iv = __fdiv_rn(g2[tid], __fsqrt_rn(v2[tid] + EPSBN));
        inv2[tid] = iv; bia2[tid] = __fmaf_rn(-m2[tid], iv, b2[tid]);
        ws_s[tid] = g_ws1[tid];
    }
    if (tid < 64) rs_s[tid] = 0;
    #pragma unroll
    for (int it = 0; it < 64; it++){
        int f = it*256 + tid;
        Ws[(f>>7)*132 + (f&127)] = g_wq1_32[f];
    }
    __syncthreads();

    float mnA = g_qp[0], sA = g_qp[1], rA = g_qp[2];

    // ---- build quantized u8 activation tile A [64px][512ci] ----
    {
        int px = tid & 63, q4 = tid >> 6;
        int p = p0 + px;
        u32 base = (u32)((p/HW)*(C1*HW) + (p%HW));
        int ci0 = q4 * 128;
        int lsum = 0;
        #pragma unroll 8
        for (int m = 0; m < 32; m++){
            int ci = ci0 + 4*m;
            u32 pack = 0;
            #pragma unroll
            for (int j = 0; j < 4; j++){
                float xv = x[base + (u32)(ci+j)*HW];
                float a = fmaxf(__fmaf_rn(xv, inv1[ci+j], bia1[ci+j]), 0.f);
                int q = qidx(a, mnA, sA, rA);
                pack |= (u32)q << (8*j);
                lsum += q;
            }
            As[px*132 + q4*32 + m] = pack;
        }
        atomicAdd(&rs_s[px], lsum);
    }
    __syncthreads();

    // ---- IMMA mainloop: warp computes 16px x 64co ----
    int r0 = (wid >> 1) * 16;
    int c0 = (wid & 1) * 64;
    int acc[8][4];
    #pragma unroll
    for (int ct = 0; ct < 8; ct++)
        #pragma unroll
        for (int d = 0; d < 4; d++) acc[ct][d] = 0;

    #pragma unroll 4
    for (int kk = 0; kk < 16; kk++){
        int kg0 = kk*8;
        u32 a0 = As[(r0 + g)*132     + kg0 + tg];
        u32 a1 = As[(r0 + 8 + g)*132 + kg0 + tg];
        u32 a2 = As[(r0 + g)*132     + kg0 + 4 + tg];
        u32 a3 = As[(r0 + 8 + g)*132 + kg0 + 4 + tg];
        #pragma unroll
        for (int ct = 0; ct < 8; ct++){
            int co = c0 + ct*8 + g;
            u32 b0 = Ws[co*132 + kg0 + tg];
            u32 b1 = Ws[co*132 + kg0 + 4 + tg];
            imma(acc[ct], a0, a1, a2, a3, b0, b1);
        }
    }
    __syncthreads();

    // ---- epilogue ----
    float mnW = g_qp[3], sW = g_qp[4];
    float SS = sA * sW;
    float c0f = 512.0f * mnA * mnW;
    float* fo = (float*)As;
    float lmin = 3.4e38f, lmax = -3.4e38f;
    #pragma unroll
    for (int hh = 0; hh < 2; hh++){
        int px = r0 + hh*8 + g;
        float t1 = __fmaf_rn(sA*mnW, (float)rs_s[px], c0f);
        #pragma unroll
        for (int ct = 0; ct < 8; ct++){
            #pragma unroll
            for (int e = 0; e < 2; e++){
                int co = c0 + ct*8 + 2*tg + e;
                float h = __fmaf_rn(SS, (float)acc[ct][hh*2+e],
                          __fmaf_rn(mnA*sW, (float)ws_s[co], t1));
                float a2v = fmaxf(__fmaf_rn(h, inv2[co], bia2[co]), 0.f);
                fo[px*132 + co] = a2v;
                lmin = fminf(lmin, a2v); lmax = fmaxf(lmax, a2v);
            }
        }
    }
    u32 emin = __reduce_min_sync(0xffffffffu, fenc(lmin));
    u32 emax = __reduce_max_sync(0xffffffffu, fenc(lmax));
    if (lane == 0){ red[wid] = emin; red[8+wid] = emax; }
    __syncthreads();
    if (tid == 0){
        u32 mn = red[0], mx = red[8];
        for (int i = 1; i < 8; i++){ mn = min(mn, red[i]); mx = max(mx, red[8+i]); }
        atomicMin(&g_mm[6], mn); atomicMax(&g_mm[7], mx);
    }
    #pragma unroll
    for (int it = 0; it < 8; it++){
        int f = it*256 + tid;
        int pxi = f >> 5, j = f & 31;
        float4 v = *(float4*)&fo[pxi*132 + j*4];
        *(float4*)&g_a2[(size_t)(p0 + pxi)*C2 + j*4] = v;
    }
}

// ---------------- K4: quantize a2 ----------------
__global__ void k_qa2(){
    int warp = threadIdx.x >> 5, lane = threadIdx.x & 31;
    int p = blockIdx.x*8 + warp;
    float mn = fdec(g_mm[6]), mx = fdec(g_mm[7]);
    float s = fmaxf(__fdiv_rn(mx - mn, 255.0f), 1e-8f), r = __frcp_rn(s);
    const float4* a4 = (const float4*)&g_a2[(size_t)p*C2];
    float4 v = a4[lane];
    int q0 = qidx(v.x, mn, s, r);
    int q1 = qidx(v.y, mn, s, r);
    int q2 = qidx(v.z, mn, s, r);
    int q3 = qidx(v.w, mn, s, r);
    g_aq2[(size_t)p*32 + lane] = (u32)q0 | ((u32)q1<<8) | ((u32)q2<<16) | ((u32)q3<<24);
    int sum = __reduce_add_sync(0xffffffffu, q0+q1+q2+q3);
    if (lane == 0) g_rs2[p] = sum;
}

// ---------------- K5: 3x3 conv via IMMA ----------------
__global__ __launch_bounds__(128) void k_conv2(float* __restrict__ out){
    __shared__ u32 Ws[32*292];      // [co][288 words], stride 292
    __shared__ u32 a_t[3*30*36];    // [row][col(halo)][32 words], stride 36
    __shared__ int   rs_s[3*30];
    __shared__ float rsum_p[28];
    __shared__ float wvL[32], wvM[32], wvR[32];

    int tid = threadIdx.x;
    int b = blockIdx.x;
    int n = b / 28, h = b % 28;
    int wid = tid >> 5, lane = tid & 31;
    int g = lane >> 2, tg = lane & 3;

    for (int f = tid; f < 9216; f += 128){
        int co = f / 288, k = f - co*288;
        Ws[co*292 + k] = g_wq2c[f];
    }
    for (int f = tid; f < 3*30*36; f += 128) a_t[f] = 0;
    if (tid < 90) rs_s[tid] = 0;
    __syncthreads();
    for (int f = tid; f < 3*28*32; f += 128){
        int rr = f / (28*32); int rem = f - rr*28*32;
        int col = rem >> 5, k = rem & 31;
        int gh = h + rr - 1;
        if ((unsigned)gh < 28u)
            a_t[(rr*30 + col + 1)*36 + k] = g_aq2[(size_t)(n*HW + gh*28 + col)*32 + k];
    }
    if (tid < 84){
        int rr = tid / 28, col = tid % 28;
        int gh = h + rr - 1;
        if ((unsigned)gh < 28u) rs_s[rr*30 + col + 1] = g_rs2[n*HW + gh*28 + col];
    }
    __syncthreads();

    if (tid < 28){
        int s = 0;
        #pragma unroll
        for (int rr = 0; rr < 3; rr++)
            #pragma unroll
            for (int dw = 0; dw < 3; dw++)
                s += rs_s[rr*30 + tid + dw];
        rsum_p[tid] = (float)s;
    }
    if (tid < 32){
        int co = tid;
        float m = 0.f, l = 0.f, r_ = 0.f;
        #pragma unroll
        for (int rr = 0; rr < 3; rr++){
            if ((unsigned)(h + rr - 1) < 28u){
                float w0 = (float)g_wts2[co*9 + rr*3 + 0];
                float w1 = (float)g_wts2[co*9 + rr*3 + 1];
                float w2 = (float)g_wts2[co*9 + rr*3 + 2];
                m  += w0 + w1 + w2;
                l  += w1 + w2;
                r_ += w0 + w1;
            }
        }
        wvM[co] = m; wvL[co] = l; wvR[co] = r_;
    }
    __syncthreads();

    int acc[2][4];
    #pragma unroll
    for (int i = 0; i < 2; i++)
        #pragma unroll
        for (int d = 0; d < 4; d++) acc[i][d] = 0;

    #pragma unroll
    for (int s = 0; s < 36; s++){
        int tap = s >> 2, chunk = s & 3;
        int rr = tap / 3, dw = tap - rr*3;
        int w0 = chunk*8 + tg;
        u32 b0 = Ws[(wid*8 + g)*292 + s*8 + tg];
        u32 b1 = Ws[(wid*8 + g)*292 + s*8 + 4 + tg];
        int rbase = rr*30 + dw;
        u32 a0 = a_t[(rbase + g)*36      + w0];
        u32 a1 = a_t[(rbase + 8 + g)*36  + w0];
        u32 a2 = a_t[(rbase + g)*36      + w0 + 4];
        u32 a3 = a_t[(rbase + 8 + g)*36  + w0 + 4];
        imma(acc[0], a0, a1, a2, a3, b0, b1);
        u32 c0 = a_t[(rbase + 16 + g)*36 + w0];
        u32 c1 = a_t[(rbase + 24 + g)*36 + w0];
        u32 c2 = a_t[(rbase + 16 + g)*36 + w0 + 4];
        u32 c3 = a_t[(rbase + 24 + g)*36 + w0 + 4];
        imma(acc[1], c0, c1, c2, c3, b0, b1);
    }

    float mnA2 = fdec(g_mm[6]), mxA2 = fdec(g_mm[7]);
    float sA2 = fmaxf(__fdiv_rn(mxA2 - mnA2, 255.0f), 1e-8f);
    float mnW = g_qp[6], sW = g_qp[7];
    float rowv = 0.f;
    #pragma unroll
    for (int rr = 0; rr < 3; rr++) rowv += ((unsigned)(h + rr - 1) < 28u) ? 1.f : 0.f;
    float SS = sA2 * sW;
    #pragma unroll
    for (int ti = 0; ti < 2; ti++){
        #pragma unroll
        for (int hh = 0; hh < 2; hh++){
            int px = ti*16 + hh*8 + g;
            if (px < 28){
                float colv = (px == 0 || px == 27) ? 2.f : 3.f;
                float nv   = rowv * colv * 128.0f;
                float rp   = rsum_p[px];
                #pragma unroll
                for (int e = 0; e < 2; e++){
                    int co = wid*8 + 2*tg + e;
                    float wvv = (px == 0) ? wvL[co] : ((px == 27) ? wvR[co] : wvM[co]);
                    float o = __fmaf_rn(SS, (float)acc[ti][hh*2+e],
                              __fmaf_rn(sA2*mnW, rp,
                              __fmaf_rn(mnA2*sW, wvv, mnA2*mnW*nv)));
                    out[((size_t)n*32 + co)*HW + h*28 + px] = o;
                }
            }
        }
    }
}

extern "C" void kernel_launch(void* const* d_in, const int* in_sizes, int n_in,
                              void* d_out, int out_size){
    const float* x  = (const float*)d_in[0];
    const float* g1 = (const float*)d_in[1];
    const float* b1 = (const float*)d_in[2];
    const float* m1 = (const float*)d_in[3];
    const float* v1 = (const float*)d_in[4];
    const float* w1 = (const float*)d_in[5];
    const float* g2 = (const float*)d_in[6];
    const float* b2 = (const float*)d_in[7];
    const float* m2 = (const float*)d_in[8];
    const float* v2 = (const float*)d_in[9];
    const float* w2 = (const float*)d_in[10];
    float* out = (float*)d_out;

    cudaFuncSetAttribute(k_conv1, cudaFuncAttributeMaxDynamicSharedMemorySize, DYN_SMEM);

    k_mm   <<<528, 256>>>(x, w1, w2);
    k_prep <<<161, 256>>>(w1, w2, g1, b1, m1, v1);
    k_conv1<<<784, 256, DYN_SMEM>>>(x, g1, b1, m1, v1, g2, b2, m2, v2);
    k_qa2  <<<6272, 256>>>();
    k_conv2<<<1792, 128>>>(out);
}

// round 10
// speedup vs baseline: 1.4273x; 1.0220x over previous
#include <cuda_runtime.h>
#include <cstdint>

typedef unsigned int u32;

#define EPSBN 1e-5f
#define C1 512
#define C2 128
#define C3 32
#define HW 784
#define PTOT (64*HW)     // 50176

// ---------------- device scratch ----------------
__device__ float g_cmn[C1], g_cmx[C1];       // per-channel raw x min/max
__device__ u32   g_wpmn[16], g_wpmx[16];     // w1 (0..7) / w2 (8..15) encoded partials
__device__ u32   g_mm[8];                    // [6,7] = a2 min/max atomics
__device__ float g_qp[12];                   // [0..2]=a1 [3..5]=w1 [6..8]=w2  (mn,s,rcp)
__device__ u32   g_wq1_32[C2*C1/4];          // w1 u8 packed [co][128]
__device__ int   g_ws1[C2];                  // per-co w1 index sums
__device__ u32   g_wq2c[C3*288];             // w2 u8 packed [co][tap*32+kg]  (co-major)
__device__ int   g_wts2[C3*9];               // per-(co,tap) w2 index sums
__device__ float g_a2[(size_t)PTOT*C2];      // relu(bn2(h)) fp32 NHWC (25.7MB)
__device__ u32   g_aq2[(size_t)PTOT*32];     // quantized a2 u8x4 NHWC (6.4MB)
__device__ int   g_rs2[PTOT];                // per-pixel a2 index sums

// ---------------- helpers ----------------
__device__ __forceinline__ u32 fenc(float f){
    u32 u = __float_as_uint(f);
    return (u & 0x80000000u) ? ~u : (u | 0x80000000u);
}
__device__ __forceinline__ float fdec(u32 e){
    return __uint_as_float((e & 0x80000000u) ? (e & 0x7fffffffu) : ~e);
}
__device__ __forceinline__ int qidx(float v, float mn, float s, float r){
    float t  = __fsub_rn(v, mn);
    float q0 = __fmul_rn(t, r);
    float q  = __fmaf_rn(__fmaf_rn(-s, q0, t), r, q0);
    int i = __float2int_rn(q);
    i = i < 0 ? 0 : i;
    return i > 255 ? 255 : i;
}
// u8 IMMA: D(16x8,s32) += A(16x32,u8,row) * B(32x8,u8,col)
__device__ __forceinline__ void imma(int* c, u32 a0, u32 a1, u32 a2, u32 a3, u32 b0, u32 b1){
    asm volatile("mma.sync.aligned.m16n8k32.row.col.s32.u8.u8.s32 "
                 "{%0,%1,%2,%3},{%4,%5,%6,%7},{%8,%9},{%0,%1,%2,%3};"
                 : "+r"(c[0]), "+r"(c[1]), "+r"(c[2]), "+r"(c[3])
                 : "r"(a0), "r"(a1), "r"(a2), "r"(a3), "r"(b0), "r"(b1));
}

// ---------------- K1: raw min/max ----------------
__global__ __launch_bounds__(256) void k_mm(const float* __restrict__ x,
                     const float* __restrict__ w1, const float* __restrict__ w2){
    __shared__ float rmn[8], rmx[8];
    __shared__ u32 wmin[8], wmax[8];
    int b = blockIdx.x, t = threadIdx.x;
    if (b < 512){
        const float4* x4 = (const float4*)x;
        float mn = 3.4e38f, mx = -3.4e38f;
        #pragma unroll 7
        for (int k = 0; k < 49; k++){
            int i = t + k*256;
            int n = i / 196, rr = i - n*196;
            float4 v = x4[((size_t)n*C1 + b)*196 + rr];
            mn = fminf(mn, fminf(fminf(v.x, v.y), fminf(v.z, v.w)));
            mx = fmaxf(mx, fmaxf(fmaxf(v.x, v.y), fmaxf(v.z, v.w)));
        }
        #pragma unroll
        for (int off = 16; off; off >>= 1){
            mn = fminf(mn, __shfl_xor_sync(0xffffffffu, mn, off));
            mx = fmaxf(mx, __shfl_xor_sync(0xffffffffu, mx, off));
        }
        if ((t & 31) == 0){ rmn[t>>5] = mn; rmx[t>>5] = mx; }
        __syncthreads();
        if (t == 0){
            for (int i = 1; i < 8; i++){ mn = fminf(mn, rmn[i]); mx = fmaxf(mx, rmx[i]); }
            g_cmn[b] = mn; g_cmx[b] = mx;
        }
    } else {
        float lmin = 3.4e38f, lmax = -3.4e38f;
        int slot;
        if (b < 520){
            slot = b - 512;
            int s0 = slot*8192;
            for (int i = t; i < 8192; i += 256){
                float v = w1[s0+i];
                lmin = fminf(lmin, v); lmax = fmaxf(lmax, v);
            }
        } else {
            slot = 8 + (b - 520);
            int s0 = (b-520)*4608;
            for (int i = t; i < 4608; i += 256){
                float v = w2[s0+i];
                lmin = fminf(lmin, v); lmax = fmaxf(lmax, v);
            }
        }
        u32 emin = __reduce_min_sync(0xffffffffu, fenc(lmin));
        u32 emax = __reduce_max_sync(0xffffffffu, fenc(lmax));
        if ((t & 31) == 0){ wmin[t>>5] = emin; wmax[t>>5] = emax; }
        __syncthreads();
        if (t == 0){
            u32 mn = wmin[0], mx = wmax[0];
            for (int i = 1; i < 8; i++){ mn = min(mn, wmin[i]); mx = max(mx, wmax[i]); }
            g_wpmn[slot] = mn; g_wpmx[slot] = mx;
        }
    }
}

// ---------------- K2: params + weight quantization ----------------
__global__ void k_prep(const float* __restrict__ w1, const float* __restrict__ w2,
                       const float* __restrict__ g1, const float* __restrict__ b1,
                       const float* __restrict__ m1, const float* __restrict__ v1){
    __shared__ int ss[9];
    __shared__ float red[64];
    int b = blockIdx.x, t = threadIdx.x;
    if (b < 128){
        u32 emn = g_wpmn[0], emx = g_wpmx[0];
        #pragma unroll
        for (int i = 1; i < 8; i++){ emn = min(emn, g_wpmn[i]); emx = max(emx, g_wpmx[i]); }
        float mn = fdec(emn), mx = fdec(emx);
        float s = fmaxf(__fdiv_rn(mx - mn, 255.0f), 1e-8f), r = __frcp_rn(s);
        int co = b;
        int lsum = 0;
        if (t < 128){
            u32 pack = 0;
            #pragma unroll
            for (int j = 0; j < 4; j++){
                int q = qidx(w1[co*C1 + 4*t + j], mn, s, r);
                pack |= (u32)q << (8*j);
                lsum += q;
            }
            g_wq1_32[co*128 + t] = pack;
        }
        lsum = __reduce_add_sync(0xffffffffu, lsum);
        if ((t & 31) == 0) ss[t>>5] = lsum;
        __syncthreads();
        if (t == 0){
            g_ws1[co] = ss[0] + ss[1] + ss[2] + ss[3];
            if (co == 0){ g_qp[3]=mn; g_qp[4]=s; g_qp[5]=r; }
        }
    } else if (b < 160){
        int co = b - 128;
        u32 emn = g_wpmn[8], emx = g_wpmx[8];
        #pragma unroll
        for (int i = 1; i < 8; i++){ emn = min(emn, g_wpmn[8+i]); emx = max(emx, g_wpmx[8+i]); }
        float mn = fdec(emn), mx = fdec(emx);
        float s = fmaxf(__fdiv_rn(mx - mn, 255.0f), 1e-8f), r = __frcp_rn(s);
        if (t < 9) ss[t] = 0;
        __syncthreads();
        for (int f = t; f < 288; f += 256){
            int tap = f >> 5, kg = f & 31;
            u32 pack = 0; int psum = 0;
            #pragma unroll
            for (int j = 0; j < 4; j++){
                int ci = kg*4 + j;
                int q = qidx(w2[co*1152 + ci*9 + tap], mn, s, r);
                pack |= (u32)q << (8*j);
                psum += q;
            }
            g_wq2c[co*288 + f] = pack;
            atomicAdd(&ss[tap], psum);
        }
        __syncthreads();
        if (t < 9) g_wts2[co*9 + t] = ss[t];
        if (t == 0 && co == 0){ g_qp[6]=mn; g_qp[7]=s; g_qp[8]=r; }
    } else {
        float gmn = 3.4e38f, gmx = -3.4e38f;
        for (int c = t; c < C1; c += 256){
            float iv = __fdiv_rn(g1[c], __fsqrt_rn(v1[c] + EPSBN));
            float bb = __fmaf_rn(-m1[c], iv, b1[c]);
            float v0 = __fmaf_rn(iv, g_cmn[c], bb);
            float v1_ = __fmaf_rn(iv, g_cmx[c], bb);
            float lo = fmaxf(fminf(v0, v1_), 0.f);
            float hi = fmaxf(fmaxf(v0, v1_), 0.f);
            gmn = fminf(gmn, lo);
            gmx = fmaxf(gmx, hi);
        }
        #pragma unroll
        for (int off = 16; off; off >>= 1){
            gmn = fminf(gmn, __shfl_xor_sync(0xffffffffu, gmn, off));
            gmx = fmaxf(gmx, __shfl_xor_sync(0xffffffffu, gmx, off));
        }
        if ((t & 31) == 0){ red[t>>5] = gmn; red[32 + (t>>5)] = gmx; }
        __syncthreads();
        if (t == 0){
            float mn = red[0], mx = red[32];
            for (int i = 1; i < 8; i++){ mn = fminf(mn, red[i]); mx = fmaxf(mx, red[32+i]); }
            float s = fmaxf(__fdiv_rn(mx - mn, 255.0f), 1e-8f);
            g_qp[0] = mn; g_qp[1] = s; g_qp[2] = __frcp_rn(s);
            g_mm[6] = 0xFFFFFFFFu; g_mm[7] = 0u;
        }
    }
}

// ---------------- K3: conv1 via IMMA, 64px tiles, 2 CTA/SM ----------------
#define AS_U32   (64*132)         // 8448
#define WS_U32   (128*132)        // 16896
#define SP_U32   (AS_U32+WS_U32)  // 25344
#define DYN_SMEM (SP_U32*4 + 6400)

__global__ __launch_bounds__(256,2) void k_conv1(
    const float* __restrict__ x,
    const float* __restrict__ g1, const float* __restrict__ b1,
    const float* __restrict__ m1, const float* __restrict__ v1,
    const float* __restrict__ g2, const float* __restrict__ b2,
    const float* __restrict__ m2, const float* __restrict__ v2)
{
    extern __shared__ __align__(16) u32 sm[];
    u32* As = sm;
    u32* Ws = sm + AS_U32;
    float* inv1 = (float*)(sm + SP_U32);
    float* bia1 = inv1 + 512;
    float* inv2 = bia1 + 512;
    float* bia2 = inv2 + 128;
    int*   ws_s = (int*)(bia2 + 128);
    int*   rs_s = ws_s + 128;
    u32*   red  = (u32*)(rs_s + 64);

    int tid = threadIdx.x, wid = tid >> 5, lane = tid & 31;
    int g = lane >> 2, tg = lane & 3;
    int p0 = blockIdx.x * 64;

    for (int c = tid; c < C1; c += 256){
        float iv = __fdiv_rn(g1[c], __fsqrt_rn(v1[c] + EPSBN));
        inv1[c] = iv; bia1[c] = __fmaf_rn(-m1[c], iv, b1[c]);
    }
    if (tid < 128){
        float iv = __fdiv_rn(g2[tid], __fsqrt_rn(v2[tid] + EPSBN));
        inv2[tid] = iv; bia2[tid] = __fmaf_rn(-m2[tid], iv, b2[tid]);
        ws_s[tid] = g_ws1[tid];
    }
    if (tid < 64) rs_s[tid] = 0;
    #pragma unroll
    for (int it = 0; it < 64; it++){
        int f = it*256 + tid;
        Ws[(f>>7)*132 + (f&127)] = g_wq1_32[f];
    }
    __syncthreads();

    float mnA = g_qp[0], sA = g_qp[1], rA = g_qp[2];

    // ---- build quantized u8 activation tile A [64px][512ci] ----
    {
        int px = tid & 63, q4 = tid >> 6;
        int p = p0 + px;
        u32 base = (u32)((p/HW)*(C1*HW) + (p%HW));
        int ci0 = q4 * 128;
        int lsum = 0;
        #pragma unroll 8
        for (int m = 0; m < 32; m++){
            int ci = ci0 + 4*m;
            u32 pack = 0;
            #pragma unroll
            for (int j = 0; j < 4; j++){
                float xv = x[base + (u32)(ci+j)*HW];
                float a = fmaxf(__fmaf_rn(xv, inv1[ci+j], bia1[ci+j]), 0.f);
                int q = qidx(a, mnA, sA, rA);
                pack |= (u32)q << (8*j);
                lsum += q;
            }
            As[px*132 + q4*32 + m] = pack;
        }
        atomicAdd(&rs_s[px], lsum);
    }
    __syncthreads();

    // ---- IMMA mainloop: warp computes 16px x 64co ----
    int r0 = (wid >> 1) * 16;
    int c0 = (wid & 1) * 64;
    int acc[8][4];
    #pragma unroll
    for (int ct = 0; ct < 8; ct++)
        #pragma unroll
        for (int d = 0; d < 4; d++) acc[ct][d] = 0;

    #pragma unroll 4
    for (int kk = 0; kk < 16; kk++){
        int kg0 = kk*8;
        u32 a0 = As[(r0 + g)*132     + kg0 + tg];
        u32 a1 = As[(r0 + 8 + g)*132 + kg0 + tg];
        u32 a2 = As[(r0 + g)*132     + kg0 + 4 + tg];
        u32 a3 = As[(r0 + 8 + g)*132 + kg0 + 4 + tg];
        #pragma unroll
        for (int ct = 0; ct < 8; ct++){
            int co = c0 + ct*8 + g;
            u32 b0 = Ws[co*132 + kg0 + tg];
            u32 b1 = Ws[co*132 + kg0 + 4 + tg];
            imma(acc[ct], a0, a1, a2, a3, b0, b1);
        }
    }
    __syncthreads();

    // ---- epilogue ----
    float mnW = g_qp[3], sW = g_qp[4];
    float SS = sA * sW;
    float c0f = 512.0f * mnA * mnW;
    float* fo = (float*)As;
    float lmin = 3.4e38f, lmax = -3.4e38f;
    #pragma unroll
    for (int hh = 0; hh < 2; hh++){
        int px = r0 + hh*8 + g;
        float t1 = __fmaf_rn(sA*mnW, (float)rs_s[px], c0f);
        #pragma unroll
        for (int ct = 0; ct < 8; ct++){
            #pragma unroll
            for (int e = 0; e < 2; e++){
                int co = c0 + ct*8 + 2*tg + e;
                float h = __fmaf_rn(SS, (float)acc[ct][hh*2+e],
                          __fmaf_rn(mnA*sW, (float)ws_s[co], t1));
                float a2v = fmaxf(__fmaf_rn(h, inv2[co], bia2[co]), 0.f);
                fo[px*132 + co] = a2v;
                lmin = fminf(lmin, a2v); lmax = fmaxf(lmax, a2v);
            }
        }
    }
    u32 emin = __reduce_min_sync(0xffffffffu, fenc(lmin));
    u32 emax = __reduce_max_sync(0xffffffffu, fenc(lmax));
    if (lane == 0){ red[wid] = emin; red[8+wid] = emax; }
    __syncthreads();
    if (tid == 0){
        u32 mn = red[0], mx = red[8];
        for (int i = 1; i < 8; i++){ mn = min(mn, red[i]); mx = max(mx, red[8+i]); }
        atomicMin(&g_mm[6], mn); atomicMax(&g_mm[7], mx);
    }
    #pragma unroll
    for (int it = 0; it < 8; it++){
        int f = it*256 + tid;
        int pxi = f >> 5, j = f & 31;
        float4 v = *(float4*)&fo[pxi*132 + j*4];
        *(float4*)&g_a2[(size_t)(p0 + pxi)*C2 + j*4] = v;
    }
}

// ---------------- K4: quantize a2 ----------------
__global__ void k_qa2(){
    int warp = threadIdx.x >> 5, lane = threadIdx.x & 31;
    int p = blockIdx.x*8 + warp;
    float mn = fdec(g_mm[6]), mx = fdec(g_mm[7]);
    float s = fmaxf(__fdiv_rn(mx - mn, 255.0f), 1e-8f), r = __frcp_rn(s);
    const float4* a4 = (const float4*)&g_a2[(size_t)p*C2];
    float4 v = a4[lane];
    int q0 = qidx(v.x, mn, s, r);
    int q1 = qidx(v.y, mn, s, r);
    int q2 = qidx(v.z, mn, s, r);
    int q3 = qidx(v.w, mn, s, r);
    g_aq2[(size_t)p*32 + lane] = (u32)q0 | ((u32)q1<<8) | ((u32)q2<<16) | ((u32)q3<<24);
    int sum = __reduce_add_sync(0xffffffffu, q0+q1+q2+q3);
    if (lane == 0) g_rs2[p] = sum;
}

// ---------------- K5: 3x3 conv via IMMA, 2 output rows per block ----------------
#define AT_ROWS 134   // 4*30 rows + slack for discarded m=28..31 fragment reads
__global__ __launch_bounds__(256) void k_conv2(float* __restrict__ out){
    __shared__ u32 Ws[32*292];          // [co][288 words], stride 292
    __shared__ u32 a_t[AT_ROWS*36];     // [4 rows x 30 halo cols][32 words], stride 36
    __shared__ int   rs_s[4*30];
    __shared__ float rsum_p[2][28];
    __shared__ float wvL[2][32], wvM[2][32], wvR[2][32];

    int tid = threadIdx.x;
    int b = blockIdx.x;
    int n = b / 14, hp = b % 14, h0 = hp*2;
    int wid = tid >> 5, lane = tid & 31;
    int g = lane >> 2, tg = lane & 3;

    for (int f = tid; f < 9216; f += 256){
        int co = f / 288, k = f - co*288;
        Ws[co*292 + k] = g_wq2c[f];
    }
    for (int f = tid; f < AT_ROWS*36; f += 256) a_t[f] = 0;
    if (tid < 120) rs_s[tid] = 0;
    __syncthreads();
    // fill 4 input rows (h0-1 .. h0+2) with halo col offset +1
    for (int f = tid; f < 4*28*32; f += 256){
        int rr = f / (28*32); int rem = f - rr*28*32;
        int col = rem >> 5, k = rem & 31;
        int gh = h0 + rr - 1;
        if ((unsigned)gh < 28u)
            a_t[(rr*30 + col + 1)*36 + k] = g_aq2[(size_t)(n*HW + gh*28 + col)*32 + k];
    }
    if (tid < 112){
        int rr = tid / 28, col = tid % 28;
        int gh = h0 + rr - 1;
        if ((unsigned)gh < 28u) rs_s[rr*30 + col + 1] = g_rs2[n*HW + gh*28 + col];
    }
    __syncthreads();

    if (tid < 56){
        int orow = tid / 28, px = tid % 28;
        int ssum = 0;
        #pragma unroll
        for (int rr = 0; rr < 3; rr++)
            #pragma unroll
            for (int dw = 0; dw < 3; dw++)
                ssum += rs_s[(orow + rr)*30 + px + dw];
        rsum_p[orow][px] = (float)ssum;
    }
    if (tid >= 64 && tid < 128){
        int t2 = tid - 64;
        int orow = t2 >> 5, co = t2 & 31;
        int h = h0 + orow;
        float m = 0.f, l = 0.f, r_ = 0.f;
        #pragma unroll
        for (int rr = 0; rr < 3; rr++){
            if ((unsigned)(h + rr - 1) < 28u){
                float w0 = (float)g_wts2[co*9 + rr*3 + 0];
                float w1 = (float)g_wts2[co*9 + rr*3 + 1];
                float w2 = (float)g_wts2[co*9 + rr*3 + 2];
                m  += w0 + w1 + w2;
                l  += w1 + w2;
                r_ += w0 + w1;
            }
        }
        wvM[orow][co] = m; wvL[orow][co] = l; wvR[orow][co] = r_;
    }
    __syncthreads();

    // ---- IMMA: warp (orow, cb) handles output row h0+orow, co block cb*8 ----
    int orow = wid >> 2, cb = wid & 3;
    int acc[2][4];
    #pragma unroll
    for (int i = 0; i < 2; i++)
        #pragma unroll
        for (int d = 0; d < 4; d++) acc[i][d] = 0;

    #pragma unroll
    for (int s = 0; s < 36; s++){
        int tap = s >> 2;
        int rr = tap / 3, dw = tap - rr*3;
        int w0 = (s & 3)*8 + tg;
        u32 b0 = Ws[(cb*8 + g)*292 + s*8 + tg];
        u32 b1 = Ws[(cb*8 + g)*292 + s*8 + 4 + tg];
        int rbase = (orow + rr)*30 + dw;
        u32 a0 = a_t[(rbase + g)*36      + w0];
        u32 a1 = a_t[(rbase + 8 + g)*36  + w0];
        u32 a2 = a_t[(rbase + g)*36      + w0 + 4];
        u32 a3 = a_t[(rbase + 8 + g)*36  + w0 + 4];
        imma(acc[0], a0, a1, a2, a3, b0, b1);
        u32 c0 = a_t[(rbase + 16 + g)*36 + w0];
        u32 c1 = a_t[(rbase + 24 + g)*36 + w0];
        u32 c2 = a_t[(rbase + 16 + g)*36 + w0 + 4];
        u32 c3 = a_t[(rbase + 24 + g)*36 + w0 + 4];
        imma(acc[1], c0, c1, c2, c3, b0, b1);
    }

    // ---- epilogue ----
    float mnA2 = fdec(g_mm[6]), mxA2 = fdec(g_mm[7]);
    float sA2 = fmaxf(__fdiv_rn(mxA2 - mnA2, 255.0f), 1e-8f);
    float mnW = g_qp[6], sW = g_qp[7];
    int h = h0 + orow;
    float rowv = 0.f;
    #pragma unroll
    for (int rr = 0; rr < 3; rr++) rowv += ((unsigned)(h + rr - 1) < 28u) ? 1.f : 0.f;
    float SS = sA2 * sW;
    #pragma unroll
    for (int ti = 0; ti < 2; ti++){
        #pragma unroll
        for (int hh = 0; hh < 2; hh++){
            int px = ti*16 + hh*8 + g;
            if (px < 28){
                float colv = (px == 0 || px == 27) ? 2.f : 3.f;
                float nv   = rowv * colv * 128.0f;
                float rp   = rsum_p[orow][px];
                #pragma unroll
                for (int e = 0; e < 2; e++){
                    int co = cb*8 + 2*tg + e;
                    float wvv = (px == 0) ? wvL[orow][co] : ((px == 27) ? wvR[orow][co] : wvM[orow][co]);
                    float o = __fmaf_rn(SS, (float)acc[ti][hh*2+e],
                              __fmaf_rn(sA2*mnW, rp,
                              __fmaf_rn(mnA2*sW, wvv, mnA2*mnW*nv)));
                    out[((size_t)n*32 + co)*HW + h*28 + px] = o;
                }
            }
        }
    }
}

extern "C" void kernel_launch(void* const* d_in, const int* in_sizes, int n_in,
                              void* d_out, int out_size){
    const float* x  = (const float*)d_in[0];
    const float* g1 = (const float*)d_in[1];
    const float* b1 = (const float*)d_in[2];
    const float* m1 = (const float*)d_in[3];
    const float* v1 = (const float*)d_in[4];
    const float* w1 = (const float*)d_in[5];
    const float* g2 = (const float*)d_in[6];
    const float* b2 = (const float*)d_in[7];
    const float* m2 = (const float*)d_in[8];
    const float* v2 = (const float*)d_in[9];
    const float* w2 = (const float*)d_in[10];
    float* out = (float*)d_out;

    cudaFuncSetAttribute(k_conv1, cudaFuncAttributeMaxDynamicSharedMemorySize, DYN_SMEM);

    k_mm   <<<528, 256>>>(x, w1, w2);
    k_prep <<<161, 256>>>(w1, w2, g1, b1, m1, v1);
    k_conv1<<<784, 256, DYN_SMEM>>>(x, g1, b1, m1, v1, g2, b2, m2, v2);
    k_qa2  <<<6272, 256>>>();
    k_conv2<<<896, 256>>>(out);
}

// round 11
// speedup vs baseline: 1.4666x; 1.0275x over previous
#include <cuda_runtime.h>
#include <cstdint>

typedef unsigned int u32;

#define EPSBN 1e-5f
#define C1 512
#define C2 128
#define C3 32
#define HW 784
#define PTOT (64*HW)     // 50176

// ---------------- device scratch ----------------
__device__ float g_cmn[C1], g_cmx[C1];       // per-channel raw x min/max
__device__ u32   g_wpmn[16], g_wpmx[16];     // w1 (0..7) / w2 (8..15) encoded partials
__device__ u32   g_mm[8];                    // [6,7] = a2 min/max atomics
__device__ float g_qp[12];                   // [0..2]=a1 [3..5]=w1 [6..8]=w2  (mn,s,rcp)
__device__ u32   g_wq1_32[C2*C1/4];          // w1 u8 packed [co][128]
__device__ int   g_ws1[C2];                  // per-co w1 index sums
__device__ u32   g_wq2c[C3*288];             // w2 u8 packed [co][tap*32+kg]  (co-major)
__device__ int   g_wts2[C3*9];               // per-(co,tap) w2 index sums
__device__ float g_a2[(size_t)PTOT*C2];      // relu(bn2(h)) fp32 NHWC (25.7MB)
__device__ u32   g_aq2[(size_t)PTOT*32];     // quantized a2 u8x4 NHWC (6.4MB)
__device__ int   g_rs2[PTOT];                // per-pixel a2 index sums

// ---------------- helpers ----------------
__device__ __forceinline__ u32 fenc(float f){
    u32 u = __float_as_uint(f);
    return (u & 0x80000000u) ? ~u : (u | 0x80000000u);
}
__device__ __forceinline__ float fdec(u32 e){
    return __uint_as_float((e & 0x80000000u) ? (e & 0x7fffffffu) : ~e);
}
__device__ __forceinline__ int qidx(float v, float mn, float s, float r){
    float t  = __fsub_rn(v, mn);
    float q0 = __fmul_rn(t, r);
    float q  = __fmaf_rn(__fmaf_rn(-s, q0, t), r, q0);
    int i = __float2int_rn(q);
    i = i < 0 ? 0 : i;
    return i > 255 ? 255 : i;
}
// u8 IMMA: D(16x8,s32) += A(16x32,u8,row) * B(32x8,u8,col)
__device__ __forceinline__ void imma(int* c, u32 a0, u32 a1, u32 a2, u32 a3, u32 b0, u32 b1){
    asm volatile("mma.sync.aligned.m16n8k32.row.col.s32.u8.u8.s32 "
                 "{%0,%1,%2,%3},{%4,%5,%6,%7},{%8,%9},{%0,%1,%2,%3};"
                 : "+r"(c[0]), "+r"(c[1]), "+r"(c[2]), "+r"(c[3])
                 : "r"(a0), "r"(a1), "r"(a2), "r"(a3), "r"(b0), "r"(b1));
}

// ---------------- K1: raw min/max ----------------
__global__ __launch_bounds__(256) void k_mm(const float* __restrict__ x,
                     const float* __restrict__ w1, const float* __restrict__ w2){
    __shared__ float rmn[8], rmx[8];
    __shared__ u32 wmin[8], wmax[8];
    int b = blockIdx.x, t = threadIdx.x;
    if (b < 512){
        const float4* x4 = (const float4*)x;
        float mn = 3.4e38f, mx = -3.4e38f;
        #pragma unroll 7
        for (int k = 0; k < 49; k++){
            int i = t + k*256;
            int n = i / 196, rr = i - n*196;
            float4 v = x4[((size_t)n*C1 + b)*196 + rr];
            mn = fminf(mn, fminf(fminf(v.x, v.y), fminf(v.z, v.w)));
            mx = fmaxf(mx, fmaxf(fmaxf(v.x, v.y), fmaxf(v.z, v.w)));
        }
        #pragma unroll
        for (int off = 16; off; off >>= 1){
            mn = fminf(mn, __shfl_xor_sync(0xffffffffu, mn, off));
            mx = fmaxf(mx, __shfl_xor_sync(0xffffffffu, mx, off));
        }
        if ((t & 31) == 0){ rmn[t>>5] = mn; rmx[t>>5] = mx; }
        __syncthreads();
        if (t == 0){
            for (int i = 1; i < 8; i++){ mn = fminf(mn, rmn[i]); mx = fmaxf(mx, rmx[i]); }
            g_cmn[b] = mn; g_cmx[b] = mx;
        }
    } else {
        float lmin = 3.4e38f, lmax = -3.4e38f;
        int slot;
        if (b < 520){
            slot = b - 512;
            int s0 = slot*8192;
            for (int i = t; i < 8192; i += 256){
                float v = w1[s0+i];
                lmin = fminf(lmin, v); lmax = fmaxf(lmax, v);
            }
        } else {
            slot = 8 + (b - 520);
            int s0 = (b-520)*4608;
            for (int i = t; i < 4608; i += 256){
                float v = w2[s0+i];
                lmin = fminf(lmin, v); lmax = fmaxf(lmax, v);
            }
        }
        u32 emin = __reduce_min_sync(0xffffffffu, fenc(lmin));
        u32 emax = __reduce_max_sync(0xffffffffu, fenc(lmax));
        if ((t & 31) == 0){ wmin[t>>5] = emin; wmax[t>>5] = emax; }
        __syncthreads();
        if (t == 0){
            u32 mn = wmin[0], mx = wmax[0];
            for (int i = 1; i < 8; i++){ mn = min(mn, wmin[i]); mx = max(mx, wmax[i]); }
            g_wpmn[slot] = mn; g_wpmx[slot] = mx;
        }
    }
}

// ---------------- K2: params + weight quantization ----------------
__global__ void k_prep(const float* __restrict__ w1, const float* __restrict__ w2,
                       const float* __restrict__ g1, const float* __restrict__ b1,
                       const float* __restrict__ m1, const float* __restrict__ v1){
    __shared__ int ss[9];
    __shared__ float red[64];
    int b = blockIdx.x, t = threadIdx.x;
    if (b < 128){
        u32 emn = g_wpmn[0], emx = g_wpmx[0];
        #pragma unroll
        for (int i = 1; i < 8; i++){ emn = min(emn, g_wpmn[i]); emx = max(emx, g_wpmx[i]); }
        float mn = fdec(emn), mx = fdec(emx);
        float s = fmaxf(__fdiv_rn(mx - mn, 255.0f), 1e-8f), r = __frcp_rn(s);
        int co = b;
        int lsum = 0;
        if (t < 128){
            u32 pack = 0;
            #pragma unroll
            for (int j = 0; j < 4; j++){
                int q = qidx(w1[co*C1 + 4*t + j], mn, s, r);
                pack |= (u32)q << (8*j);
                lsum += q;
            }
            g_wq1_32[co*128 + t] = pack;
        }
        lsum = __reduce_add_sync(0xffffffffu, lsum);
        if ((t & 31) == 0) ss[t>>5] = lsum;
        __syncthreads();
        if (t == 0){
            g_ws1[co] = ss[0] + ss[1] + ss[2] + ss[3];
            if (co == 0){ g_qp[3]=mn; g_qp[4]=s; g_qp[5]=r; }
        }
    } else if (b < 160){
        int co = b - 128;
        u32 emn = g_wpmn[8], emx = g_wpmx[8];
        #pragma unroll
        for (int i = 1; i < 8; i++){ emn = min(emn, g_wpmn[8+i]); emx = max(emx, g_wpmx[8+i]); }
        float mn = fdec(emn), mx = fdec(emx);
        float s = fmaxf(__fdiv_rn(mx - mn, 255.0f), 1e-8f), r = __frcp_rn(s);
        if (t < 9) ss[t] = 0;
        __syncthreads();
        for (int f = t; f < 288; f += 256){
            int tap = f >> 5, kg = f & 31;
            u32 pack = 0; int psum = 0;
            #pragma unroll
            for (int j = 0; j < 4; j++){
                int ci = kg*4 + j;
                int q = qidx(w2[co*1152 + ci*9 + tap], mn, s, r);
                pack |= (u32)q << (8*j);
                psum += q;
            }
            g_wq2c[co*288 + f] = pack;
            atomicAdd(&ss[tap], psum);
        }
        __syncthreads();
        if (t < 9) g_wts2[co*9 + t] = ss[t];
        if (t == 0 && co == 0){ g_qp[6]=mn; g_qp[7]=s; g_qp[8]=r; }
    } else {
        float gmn = 3.4e38f, gmx = -3.4e38f;
        for (int c = t; c < C1; c += 256){
            float iv = __fdiv_rn(g1[c], __fsqrt_rn(v1[c] + EPSBN));
            float bb = __fmaf_rn(-m1[c], iv, b1[c]);
            float v0 = __fmaf_rn(iv, g_cmn[c], bb);
            float v1_ = __fmaf_rn(iv, g_cmx[c], bb);
            float lo = fmaxf(fminf(v0, v1_), 0.f);
            float hi = fmaxf(fmaxf(v0, v1_), 0.f);
            gmn = fminf(gmn, lo);
            gmx = fmaxf(gmx, hi);
        }
        #pragma unroll
        for (int off = 16; off; off >>= 1){
            gmn = fminf(gmn, __shfl_xor_sync(0xffffffffu, gmn, off));
            gmx = fmaxf(gmx, __shfl_xor_sync(0xffffffffu, gmx, off));
        }
        if ((t & 31) == 0){ red[t>>5] = gmn; red[32 + (t>>5)] = gmx; }
        __syncthreads();
        if (t == 0){
            float mn = red[0], mx = red[32];
            for (int i = 1; i < 8; i++){ mn = fminf(mn, red[i]); mx = fmaxf(mx, red[32+i]); }
            float s = fmaxf(__fdiv_rn(mx - mn, 255.0f), 1e-8f);
            g_qp[0] = mn; g_qp[1] = s; g_qp[2] = __frcp_rn(s);
            g_mm[6] = 0xFFFFFFFFu; g_mm[7] = 0u;
        }
    }
}

// ---------------- K3: conv1 via IMMA, 64px tiles, 2 CTA/SM ----------------
#define AS_U32   (64*132)         // 8448
#define WS_U32   (128*132)        // 16896
#define SP_U32   (AS_U32+WS_U32)  // 25344
#define DYN_SMEM (SP_U32*4 + 6400)

__global__ __launch_bounds__(256,2) void k_conv1(
    const float* __restrict__ x,
    const float* __restrict__ g1, const float* __restrict__ b1,
    const float* __restrict__ m1, const float* __restrict__ v1,
    const float* __restrict__ g2, const float* __restrict__ b2,
    const float* __restrict__ m2, const float* __restrict__ v2)
{
    extern __shared__ __align__(16) u32 sm[];
    u32* As = sm;
    u32* Ws = sm + AS_U32;
    float* inv1 = (float*)(sm + SP_U32);
    float* bia1 = inv1 + 512;
    float* inv2 = bia1 + 512;
    float* bia2 = inv2 + 128;
    int*   ws_s = (int*)(bia2 + 128);
    int*   rs_s = ws_s + 128;
    u32*   red  = (u32*)(rs_s + 64);

    int tid = threadIdx.x, wid = tid >> 5, lane = tid & 31;
    int g = lane >> 2, tg = lane & 3;
    int p0 = blockIdx.x * 64;

    for (int c = tid; c < C1; c += 256){
        float iv = __fdiv_rn(g1[c], __fsqrt_rn(v1[c] + EPSBN));
        inv1[c] = iv; bia1[c] = __fmaf_rn(-m1[c], iv, b1[c]);
    }
    if (tid < 128){
        float iv = __fdiv_rn(g2[tid], __fsqrt_rn(v2[tid] + EPSBN));
        inv2[tid] = iv; bia2[tid] = __fmaf_rn(-m2[tid], iv, b2[tid]);
        ws_s[tid] = g_ws1[tid];
    }
    if (tid < 64) rs_s[tid] = 0;
    #pragma unroll
    for (int it = 0; it < 64; it++){
        int f = it*256 + tid;
        Ws[(f>>7)*132 + (f&127)] = g_wq1_32[f];
    }
    __syncthreads();

    float mnA = g_qp[0], sA = g_qp[1], rA = g_qp[2];

    // ---- build quantized u8 activation tile A [64px][512ci] ----
    {
        int px = tid & 63, q4 = tid >> 6;
        int p = p0 + px;
        u32 base = (u32)((p/HW)*(C1*HW) + (p%HW));
        int ci0 = q4 * 128;
        int lsum = 0;
        #pragma unroll 8
        for (int m = 0; m < 32; m++){
            int ci = ci0 + 4*m;
            u32 pack = 0;
            #pragma unroll
            for (int j = 0; j < 4; j++){
                float xv = x[base + (u32)(ci+j)*HW];
                float a = fmaxf(__fmaf_rn(xv, inv1[ci+j], bia1[ci+j]), 0.f);
                int q = qidx(a, mnA, sA, rA);
                pack |= (u32)q << (8*j);
                lsum += q;
            }
            As[px*132 + q4*32 + m] = pack;
        }
        atomicAdd(&rs_s[px], lsum);
    }
    __syncthreads();

    // ---- IMMA mainloop: warp computes 16px x 64co ----
    int r0 = (wid >> 1) * 16;
    int c0 = (wid & 1) * 64;
    int acc[8][4];
    #pragma unroll
    for (int ct = 0; ct < 8; ct++)
        #pragma unroll
        for (int d = 0; d < 4; d++) acc[ct][d] = 0;

    #pragma unroll 4
    for (int kk = 0; kk < 16; kk++){
        int kg0 = kk*8;
        u32 a0 = As[(r0 + g)*132     + kg0 + tg];
        u32 a1 = As[(r0 + 8 + g)*132 + kg0 + tg];
        u32 a2 = As[(r0 + g)*132     + kg0 + 4 + tg];
        u32 a3 = As[(r0 + 8 + g)*132 + kg0 + 4 + tg];
        #pragma unroll
        for (int ct = 0; ct < 8; ct++){
            int co = c0 + ct*8 + g;
            u32 b0 = Ws[co*132 + kg0 + tg];
            u32 b1 = Ws[co*132 + kg0 + 4 + tg];
            imma(acc[ct], a0, a1, a2, a3, b0, b1);
        }
    }
    __syncthreads();

    // ---- epilogue ----
    float mnW = g_qp[3], sW = g_qp[4];
    float SS = sA * sW;
    float c0f = 512.0f * mnA * mnW;
    float* fo = (float*)As;
    float lmin = 3.4e38f, lmax = -3.4e38f;
    #pragma unroll
    for (int hh = 0; hh < 2; hh++){
        int px = r0 + hh*8 + g;
        float t1 = __fmaf_rn(sA*mnW, (float)rs_s[px], c0f);
        #pragma unroll
        for (int ct = 0; ct < 8; ct++){
            #pragma unroll
            for (int e = 0; e < 2; e++){
                int co = c0 + ct*8 + 2*tg + e;
                float h = __fmaf_rn(SS, (float)acc[ct][hh*2+e],
                          __fmaf_rn(mnA*sW, (float)ws_s[co], t1));
                float a2v = fmaxf(__fmaf_rn(h, inv2[co], bia2[co]), 0.f);
                fo[px*132 + co] = a2v;
                lmin = fminf(lmin, a2v); lmax = fmaxf(lmax, a2v);
            }
        }
    }
    u32 emin = __reduce_min_sync(0xffffffffu, fenc(lmin));
    u32 emax = __reduce_max_sync(0xffffffffu, fenc(lmax));
    if (lane == 0){ red[wid] = emin; red[8+wid] = emax; }
    __syncthreads();
    if (tid == 0){
        u32 mn = red[0], mx = red[8];
        for (int i = 1; i < 8; i++){ mn = min(mn, red[i]); mx = max(mx, red[8+i]); }
        atomicMin(&g_mm[6], mn); atomicMax(&g_mm[7], mx);
    }
    #pragma unroll
    for (int it = 0; it < 8; it++){
        int f = it*256 + tid;
        int pxi = f >> 5, j = f & 31;
        float4 v = *(float4*)&fo[pxi*132 + j*4];
        *(float4*)&g_a2[(size_t)(p0 + pxi)*C2 + j*4] = v;
    }
}

// ---------------- K4: quantize a2 (4 pixels per warp, MLP=4) ----------------
__global__ void k_qa2(){
    int warp = threadIdx.x >> 5, lane = threadIdx.x & 31;
    int p = blockIdx.x*32 + warp*4;
    float mn = fdec(g_mm[6]), mx = fdec(g_mm[7]);
    float s = fmaxf(__fdiv_rn(mx - mn, 255.0f), 1e-8f), r = __frcp_rn(s);
    float4 v0 = ((const float4*)&g_a2[(size_t)(p+0)*C2])[lane];
    float4 v1 = ((const float4*)&g_a2[(size_t)(p+1)*C2])[lane];
    float4 v2 = ((const float4*)&g_a2[(size_t)(p+2)*C2])[lane];
    float4 v3 = ((const float4*)&g_a2[(size_t)(p+3)*C2])[lane];
    int q00=qidx(v0.x,mn,s,r), q01=qidx(v0.y,mn,s,r), q02=qidx(v0.z,mn,s,r), q03=qidx(v0.w,mn,s,r);
    int q10=qidx(v1.x,mn,s,r), q11=qidx(v1.y,mn,s,r), q12=qidx(v1.z,mn,s,r), q13=qidx(v1.w,mn,s,r);
    int q20=qidx(v2.x,mn,s,r), q21=qidx(v2.y,mn,s,r), q22=qidx(v2.z,mn,s,r), q23=qidx(v2.w,mn,s,r);
    int q30=qidx(v3.x,mn,s,r), q31=qidx(v3.y,mn,s,r), q32=qidx(v3.z,mn,s,r), q33=qidx(v3.w,mn,s,r);
    g_aq2[(size_t)(p+0)*32 + lane] = (u32)q00 | ((u32)q01<<8) | ((u32)q02<<16) | ((u32)q03<<24);
    g_aq2[(size_t)(p+1)*32 + lane] = (u32)q10 | ((u32)q11<<8) | ((u32)q12<<16) | ((u32)q13<<24);
    g_aq2[(size_t)(p+2)*32 + lane] = (u32)q20 | ((u32)q21<<8) | ((u32)q22<<16) | ((u32)q23<<24);
    g_aq2[(size_t)(p+3)*32 + lane] = (u32)q30 | ((u32)q31<<8) | ((u32)q32<<16) | ((u32)q33<<24);
    int s0 = __reduce_add_sync(0xffffffffu, q00+q01+q02+q03);
    int s1 = __reduce_add_sync(0xffffffffu, q10+q11+q12+q13);
    int s2 = __reduce_add_sync(0xffffffffu, q20+q21+q22+q23);
    int s3 = __reduce_add_sync(0xffffffffu, q30+q31+q32+q33);
    if (lane == 0){
        g_rs2[p+0] = s0; g_rs2[p+1] = s1; g_rs2[p+2] = s2; g_rs2[p+3] = s3;
    }
}

// ---------------- K5: 3x3 conv via IMMA, 4 output rows per block ----------------
#define AT2_ROWS 186   // 6*30 input rows + slack for discarded m=28..31 fragment reads
__global__ __launch_bounds__(256) void k_conv2(float* __restrict__ out){
    __shared__ u32 Ws[32*292];          // [co][288 words], stride 292
    __shared__ u32 a_t[AT2_ROWS*36];    // [6 rows x 30 halo cols][32 words], stride 36
    __shared__ int   rs_s[6*30];
    __shared__ float rsum_p[4][28];
    __shared__ float wvL[4][32], wvM[4][32], wvR[4][32];

    int tid = threadIdx.x;
    int b = blockIdx.x;
    int n = b / 7, hp = b % 7, h0 = hp*4;
    int wid = tid >> 5, lane = tid & 31;
    int g = lane >> 2, tg = lane & 3;

    for (int f = tid; f < 9216; f += 256){
        int co = f / 288, k = f - co*288;
        Ws[co*292 + k] = g_wq2c[f];
    }
    for (int f = tid; f < AT2_ROWS*36; f += 256) a_t[f] = 0;
    if (tid < 180) rs_s[tid] = 0;
    __syncthreads();
    // fill 6 input rows (h0-1 .. h0+4) with halo col offset +1
    for (int f = tid; f < 6*28*32; f += 256){
        int rr = f / (28*32); int rem = f - rr*28*32;
        int col = rem >> 5, k = rem & 31;
        int gh = h0 + rr - 1;
        if ((unsigned)gh < 28u)
            a_t[(rr*30 + col + 1)*36 + k] = g_aq2[(size_t)(n*HW + gh*28 + col)*32 + k];
    }
    if (tid < 168){
        int rr = tid / 28, col = tid % 28;
        int gh = h0 + rr - 1;
        if ((unsigned)gh < 28u) rs_s[rr*30 + col + 1] = g_rs2[n*HW + gh*28 + col];
    }
    __syncthreads();

    if (tid < 112){
        int orow = tid / 28, px = tid % 28;
        int ssum = 0;
        #pragma unroll
        for (int rr = 0; rr < 3; rr++)
            #pragma unroll
            for (int dw = 0; dw < 3; dw++)
                ssum += rs_s[(orow + rr)*30 + px + dw];
        rsum_p[orow][px] = (float)ssum;
    }
    if (tid >= 128){
        int t2 = tid - 128;
        int orow = t2 >> 5, co = t2 & 31;
        int h = h0 + orow;
        float m = 0.f, l = 0.f, r_ = 0.f;
        #pragma unroll
        for (int rr = 0; rr < 3; rr++){
            if ((unsigned)(h + rr - 1) < 28u){
                float w0 = (float)g_wts2[co*9 + rr*3 + 0];
                float w1 = (float)g_wts2[co*9 + rr*3 + 1];
                float w2 = (float)g_wts2[co*9 + rr*3 + 2];
                m  += w0 + w1 + w2;
                l  += w1 + w2;
                r_ += w0 + w1;
            }
        }
        wvM[orow][co] = m; wvL[orow][co] = l; wvR[orow][co] = r_;
    }
    __syncthreads();

    // ---- IMMA: warp (orow, cb) handles output row h0+orow, co block cb*16 (2 groups of 8) ----
    int orow = wid >> 1, cb = wid & 1;
    int acc[2][2][4];   // [pxhalf][cogrp][frag]
    #pragma unroll
    for (int i = 0; i < 2; i++)
        #pragma unroll
        for (int j = 0; j < 2; j++)
            #pragma unroll
            for (int d = 0; d < 4; d++) acc[i][j][d] = 0;

    #pragma unroll
    for (int s = 0; s < 36; s++){
        int tap = s >> 2;
        int rr = tap / 3, dw = tap - rr*3;
        int w0 = (s & 3)*8 + tg;
        int rbase = (orow + rr)*30 + dw;
        u32 a0 = a_t[(rbase + g)*36      + w0];
        u32 a1 = a_t[(rbase + 8 + g)*36  + w0];
        u32 a2 = a_t[(rbase + g)*36      + w0 + 4];
        u32 a3 = a_t[(rbase + 8 + g)*36  + w0 + 4];
        u32 c0 = a_t[(rbase + 16 + g)*36 + w0];
        u32 c1 = a_t[(rbase + 24 + g)*36 + w0];
        u32 c2 = a_t[(rbase + 16 + g)*36 + w0 + 4];
        u32 c3 = a_t[(rbase + 24 + g)*36 + w0 + 4];
        #pragma unroll
        for (int cg = 0; cg < 2; cg++){
            int co = cb*16 + cg*8 + g;
            u32 b0 = Ws[co*292 + s*8 + tg];
            u32 b1 = Ws[co*292 + s*8 + 4 + tg];
            imma(acc[0][cg], a0, a1, a2, a3, b0, b1);
            imma(acc[1][cg], c0, c1, c2, c3, b0, b1);
        }
    }

    // ---- epilogue ----
    float mnA2 = fdec(g_mm[6]), mxA2 = fdec(g_mm[7]);
    float sA2 = fmaxf(__fdiv_rn(mxA2 - mnA2, 255.0f), 1e-8f);
    float mnW = g_qp[6], sW = g_qp[7];
    int h = h0 + orow;
    float rowv = 0.f;
    #pragma unroll
    for (int rr = 0; rr < 3; rr++) rowv += ((unsigned)(h + rr - 1) < 28u) ? 1.f : 0.f;
    float SS = sA2 * sW;
    #pragma unroll
    for (int ti = 0; ti < 2; ti++){
        #pragma unroll
        for (int hh = 0; hh < 2; hh++){
            int px = ti*16 + hh*8 + g;
            if (px < 28){
                float colv = (px == 0 || px == 27) ? 2.f : 3.f;
                float nv   = rowv * colv * 128.0f;
                float rp   = rsum_p[orow][px];
                #pragma unroll
                for (int cg = 0; cg < 2; cg++){
                    #pragma unroll
                    for (int e = 0; e < 2; e++){
                        int co = cb*16 + cg*8 + 2*tg + e;
                        float wvv = (px == 0) ? wvL[orow][co] : ((px == 27) ? wvR[orow][co] : wvM[orow][co]);
                        float o = __fmaf_rn(SS, (float)acc[ti][cg][hh*2+e],
                                  __fmaf_rn(sA2*mnW, rp,
                                  __fmaf_rn(mnA2*sW, wvv, mnA2*mnW*nv)));
                        out[((size_t)n*32 + co)*HW + h*28 + px] = o;
                    }
                }
            }
        }
    }
}

extern "C" void kernel_launch(void* const* d_in, const int* in_sizes, int n_in,
                              void* d_out, int out_size){
    const float* x  = (const float*)d_in[0];
    const float* g1 = (const float*)d_in[1];
    const float* b1 = (const float*)d_in[2];
    const float* m1 = (const float*)d_in[3];
    const float* v1 = (const float*)d_in[4];
    const float* w1 = (const float*)d_in[5];
    const float* g2 = (const float*)d_in[6];
    const float* b2 = (const float*)d_in[7];
    const float* m2 = (const float*)d_in[8];
    const float* v2 = (const float*)d_in[9];
    const float* w2 = (const float*)d_in[10];
    float* out = (float*)d_out;

    cudaFuncSetAttribute(k_conv1, cudaFuncAttributeMaxDynamicSharedMemorySize, DYN_SMEM);

    k_mm   <<<528, 256>>>(x, w1, w2);
    k_prep <<<161, 256>>>(w1, w2, g1, b1, m1, v1);
    k_conv1<<<784, 256, DYN_SMEM>>>(x, g1, b1, m1, v1, g2, b2, m2, v2);
    k_qa2  <<<1568, 256>>>();
    k_conv2<<<448, 256>>>(out);
}

// round 12
// speedup vs baseline: 1.4917x; 1.0171x over previous
#include <cuda_runtime.h>
#include <cstdint>

typedef unsigned int u32;

#define EPSBN 1e-5f
#define C1 512
#define C2 128
#define C3 32
#define HW 784
#define PTOT (64*HW)     // 50176

// ---------------- device scratch ----------------
__device__ float g_cmn[C1], g_cmx[C1];       // per-channel raw x min/max
__device__ u32   g_wpmn[16], g_wpmx[16];     // w1 (0..7) / w2 (8..15) encoded partials
__device__ u32   g_mm[8];                    // [6,7] = a2 min/max atomics
__device__ float g_qp[12];                   // [0..2]=a1 [3..5]=w1 [6..8]=w2  (mn,s,rcp)
__device__ u32   g_wq1_32[C2*C1/4];          // w1 u8 packed [co][128]
__device__ int   g_ws1[C2];                  // per-co w1 index sums
__device__ u32   g_wq2c[C3*288];             // w2 u8 packed [co][tap*32+kg]  (co-major)
__device__ int   g_wts2[C3*9];               // per-(co,tap) w2 index sums
__device__ float g_a2[(size_t)PTOT*C2];      // relu(bn2(h)) fp32 NHWC (25.7MB)
__device__ u32   g_aq2[(size_t)PTOT*32];     // quantized a2 u8x4 NHWC (6.4MB)
__device__ int   g_rs2[PTOT];                // per-pixel a2 index sums

// ---------------- helpers ----------------
__device__ __forceinline__ u32 fenc(float f){
    u32 u = __float_as_uint(f);
    return (u & 0x80000000u) ? ~u : (u | 0x80000000u);
}
__device__ __forceinline__ float fdec(u32 e){
    return __uint_as_float((e & 0x80000000u) ? (e & 0x7fffffffu) : ~e);
}
__device__ __forceinline__ int qidx(float v, float mn, float s, float r){
    float t  = __fsub_rn(v, mn);
    float q0 = __fmul_rn(t, r);
    float q  = __fmaf_rn(__fmaf_rn(-s, q0, t), r, q0);
    int i = __float2int_rn(q);
    i = i < 0 ? 0 : i;
    return i > 255 ? 255 : i;
}
// u8 IMMA: D(16x8,s32) += A(16x32,u8,row) * B(32x8,u8,col)
__device__ __forceinline__ void imma(int* c, u32 a0, u32 a1, u32 a2, u32 a3, u32 b0, u32 b1){
    asm volatile("mma.sync.aligned.m16n8k32.row.col.s32.u8.u8.s32 "
                 "{%0,%1,%2,%3},{%4,%5,%6,%7},{%8,%9},{%0,%1,%2,%3};"
                 : "+r"(c[0]), "+r"(c[1]), "+r"(c[2]), "+r"(c[3])
                 : "r"(a0), "r"(a1), "r"(a2), "r"(a3), "r"(b0), "r"(b1));
}

// ---------------- K1: raw min/max ----------------
__global__ __launch_bounds__(256) void k_mm(const float* __restrict__ x,
                     const float* __restrict__ w1, const float* __restrict__ w2){
    __shared__ float rmn[8], rmx[8];
    __shared__ u32 wmin[8], wmax[8];
    int b = blockIdx.x, t = threadIdx.x;
    if (b < 512){
        const float4* x4 = (const float4*)x;
        float mn = 3.4e38f, mx = -3.4e38f;
        #pragma unroll 7
        for (int k = 0; k < 49; k++){
            int i = t + k*256;
            int n = i / 196, rr = i - n*196;
            float4 v = x4[((size_t)n*C1 + b)*196 + rr];
            mn = fminf(mn, fminf(fminf(v.x, v.y), fminf(v.z, v.w)));
            mx = fmaxf(mx, fmaxf(fmaxf(v.x, v.y), fmaxf(v.z, v.w)));
        }
        #pragma unroll
        for (int off = 16; off; off >>= 1){
            mn = fminf(mn, __shfl_xor_sync(0xffffffffu, mn, off));
            mx = fmaxf(mx, __shfl_xor_sync(0xffffffffu, mx, off));
        }
        if ((t & 31) == 0){ rmn[t>>5] = mn; rmx[t>>5] = mx; }
        __syncthreads();
        if (t == 0){
            for (int i = 1; i < 8; i++){ mn = fminf(mn, rmn[i]); mx = fmaxf(mx, rmx[i]); }
            g_cmn[b] = mn; g_cmx[b] = mx;
        }
    } else {
        float lmin = 3.4e38f, lmax = -3.4e38f;
        int slot;
        if (b < 520){
            slot = b - 512;
            int s0 = slot*8192;
            for (int i = t; i < 8192; i += 256){
                float v = w1[s0+i];
                lmin = fminf(lmin, v); lmax = fmaxf(lmax, v);
            }
        } else {
            slot = 8 + (b - 520);
            int s0 = (b-520)*4608;
            for (int i = t; i < 4608; i += 256){
                float v = w2[s0+i];
                lmin = fminf(lmin, v); lmax = fmaxf(lmax, v);
            }
        }
        u32 emin = __reduce_min_sync(0xffffffffu, fenc(lmin));
        u32 emax = __reduce_max_sync(0xffffffffu, fenc(lmax));
        if ((t & 31) == 0){ wmin[t>>5] = emin; wmax[t>>5] = emax; }
        __syncthreads();
        if (t == 0){
            u32 mn = wmin[0], mx = wmax[0];
            for (int i = 1; i < 8; i++){ mn = min(mn, wmin[i]); mx = max(mx, wmax[i]); }
            g_wpmn[slot] = mn; g_wpmx[slot] = mx;
        }
    }
}

// ---------------- K2: params + weight quantization ----------------
__global__ void k_prep(const float* __restrict__ w1, const float* __restrict__ w2,
                       const float* __restrict__ g1, const float* __restrict__ b1,
                       const float* __restrict__ m1, const float* __restrict__ v1){
    __shared__ int ss[9];
    __shared__ float red[64];
    int b = blockIdx.x, t = threadIdx.x;
    if (b < 128){
        u32 emn = g_wpmn[0], emx = g_wpmx[0];
        #pragma unroll
        for (int i = 1; i < 8; i++){ emn = min(emn, g_wpmn[i]); emx = max(emx, g_wpmx[i]); }
        float mn = fdec(emn), mx = fdec(emx);
        float s = fmaxf(__fdiv_rn(mx - mn, 255.0f), 1e-8f), r = __frcp_rn(s);
        int co = b;
        int lsum = 0;
        if (t < 128){
            u32 pack = 0;
            #pragma unroll
            for (int j = 0; j < 4; j++){
                int q = qidx(w1[co*C1 + 4*t + j], mn, s, r);
                pack |= (u32)q << (8*j);
                lsum += q;
            }
            g_wq1_32[co*128 + t] = pack;
        }
        lsum = __reduce_add_sync(0xffffffffu, lsum);
        if ((t & 31) == 0) ss[t>>5] = lsum;
        __syncthreads();
        if (t == 0){
            g_ws1[co] = ss[0] + ss[1] + ss[2] + ss[3];
            if (co == 0){ g_qp[3]=mn; g_qp[4]=s; g_qp[5]=r; }
        }
    } else if (b < 160){
        int co = b - 128;
        u32 emn = g_wpmn[8], emx = g_wpmx[8];
        #pragma unroll
        for (int i = 1; i < 8; i++){ emn = min(emn, g_wpmn[8+i]); emx = max(emx, g_wpmx[8+i]); }
        float mn = fdec(emn), mx = fdec(emx);
        float s = fmaxf(__fdiv_rn(mx - mn, 255.0f), 1e-8f), r = __frcp_rn(s);
        if (t < 9) ss[t] = 0;
        __syncthreads();
        for (int f = t; f < 288; f += 256){
            int tap = f >> 5, kg = f & 31;
            u32 pack = 0; int psum = 0;
            #pragma unroll
            for (int j = 0; j < 4; j++){
                int ci = kg*4 + j;
                int q = qidx(w2[co*1152 + ci*9 + tap], mn, s, r);
                pack |= (u32)q << (8*j);
                psum += q;
            }
            g_wq2c[co*288 + f] = pack;
            atomicAdd(&ss[tap], psum);
        }
        __syncthreads();
        if (t < 9) g_wts2[co*9 + t] = ss[t];
        if (t == 0 && co == 0){ g_qp[6]=mn; g_qp[7]=s; g_qp[8]=r; }
    } else {
        float gmn = 3.4e38f, gmx = -3.4e38f;
        for (int c = t; c < C1; c += 256){
            float iv = __fdiv_rn(g1[c], __fsqrt_rn(v1[c] + EPSBN));
            float bb = __fmaf_rn(-m1[c], iv, b1[c]);
            float v0 = __fmaf_rn(iv, g_cmn[c], bb);
            float v1_ = __fmaf_rn(iv, g_cmx[c], bb);
            float lo = fmaxf(fminf(v0, v1_), 0.f);
            float hi = fmaxf(fmaxf(v0, v1_), 0.f);
            gmn = fminf(gmn, lo);
            gmx = fmaxf(gmx, hi);
        }
        #pragma unroll
        for (int off = 16; off; off >>= 1){
            gmn = fminf(gmn, __shfl_xor_sync(0xffffffffu, gmn, off));
            gmx = fmaxf(gmx, __shfl_xor_sync(0xffffffffu, gmx, off));
        }
        if ((t & 31) == 0){ red[t>>5] = gmn; red[32 + (t>>5)] = gmx; }
        __syncthreads();
        if (t == 0){
            float mn = red[0], mx = red[32];
            for (int i = 1; i < 8; i++){ mn = fminf(mn, red[i]); mx = fmaxf(mx, red[32+i]); }
            float s = fmaxf(__fdiv_rn(mx - mn, 255.0f), 1e-8f);
            g_qp[0] = mn; g_qp[1] = s; g_qp[2] = __frcp_rn(s);
            g_mm[6] = 0xFFFFFFFFu; g_mm[7] = 0u;
        }
    }
}

// ---------------- K3: conv1 via IMMA, 64px tiles, 2 CTA/SM ----------------
#define AS_U32   (64*132)         // 8448
#define WS_U32   (128*132)        // 16896
#define SP_U32   (AS_U32+WS_U32)  // 25344
#define DYN_SMEM (SP_U32*4 + 6400)

__global__ __launch_bounds__(256,2) void k_conv1(
    const float* __restrict__ x,
    const float* __restrict__ g1, const float* __restrict__ b1,
    const float* __restrict__ m1, const float* __restrict__ v1,
    const float* __restrict__ g2, const float* __restrict__ b2,
    const float* __restrict__ m2, const float* __restrict__ v2)
{
    extern __shared__ __align__(16) u32 sm[];
    u32* As = sm;
    u32* Ws = sm + AS_U32;
    float* inv1 = (float*)(sm + SP_U32);
    float* bia1 = inv1 + 512;
    float* inv2 = bia1 + 512;
    float* bia2 = inv2 + 128;
    int*   ws_s = (int*)(bia2 + 128);
    int*   rs_s = ws_s + 128;
    u32*   red  = (u32*)(rs_s + 64);

    int tid = threadIdx.x, wid = tid >> 5, lane = tid & 31;
    int g = lane >> 2, tg = lane & 3;
    int p0 = blockIdx.x * 64;

    for (int c = tid; c < C1; c += 256){
        float iv = __fdiv_rn(g1[c], __fsqrt_rn(v1[c] + EPSBN));
        inv1[c] = iv; bia1[c] = __fmaf_rn(-m1[c], iv, b1[c]);
    }
    if (tid < 128){
        float iv = __fdiv_rn(g2[tid], __fsqrt_rn(v2[tid] + EPSBN));
        inv2[tid] = iv; bia2[tid] = __fmaf_rn(-m2[tid], iv, b2[tid]);
        ws_s[tid] = g_ws1[tid];
    }
    if (tid < 64) rs_s[tid] = 0;
    // weights: 16384 words as 4096 uint4
    #pragma unroll
    for (int it = 0; it < 16; it++){
        int f = it*256 + tid;          // uint4 index
        int w0 = f*4;
        uint4 v = ((const uint4*)g_wq1_32)[f];
        *(uint4*)&Ws[(w0>>7)*132 + (w0&127)] = v;
    }
    __syncthreads();

    float mnA = g_qp[0], sA = g_qp[1], rA = g_qp[2];

    // ---- build quantized u8 activation tile A [64px][512ci], float4 over pixels ----
    {
        int pg  = tid & 15;            // pixel group (4 px)
        int cig = tid >> 4;            // channel group (32 ci)
        int pxb = pg*4;
        int p = p0 + pxb;
        int n = p / HW, off = p - n*HW;   // off divisible by 4 (HW%4==0, p0%4==0, pxb%4==0)
        const float* basef = x + (size_t)n*(C1*HW) + off;
        int ci0 = cig*32;
        u32 w[4][8];                   // [px][word]
        int lsum[4] = {0,0,0,0};
        #pragma unroll 4
        for (int cc = 0; cc < 8; cc++){
            int ci = ci0 + cc*4;
            float4 v0 = *(const float4*)(basef + (size_t)(ci+0)*HW);
            float4 v1 = *(const float4*)(basef + (size_t)(ci+1)*HW);
            float4 v2 = *(const float4*)(basef + (size_t)(ci+2)*HW);
            float4 v3 = *(const float4*)(basef + (size_t)(ci+3)*HW);
            float i0 = inv1[ci+0], o0 = bia1[ci+0];
            float i1 = inv1[ci+1], o1 = bia1[ci+1];
            float i2 = inv1[ci+2], o2 = bia1[ci+2];
            float i3 = inv1[ci+3], o3 = bia1[ci+3];
            #pragma unroll
            for (int px = 0; px < 4; px++){
                float e0 = px==0?v0.x:px==1?v0.y:px==2?v0.z:v0.w;
                float e1 = px==0?v1.x:px==1?v1.y:px==2?v1.z:v1.w;
                float e2 = px==0?v2.x:px==1?v2.y:px==2?v2.z:v2.w;
                float e3 = px==0?v3.x:px==1?v3.y:px==2?v3.z:v3.w;
                int q0 = qidx(fmaxf(__fmaf_rn(e0, i0, o0), 0.f), mnA, sA, rA);
                int q1 = qidx(fmaxf(__fmaf_rn(e1, i1, o1), 0.f), mnA, sA, rA);
                int q2 = qidx(fmaxf(__fmaf_rn(e2, i2, o2), 0.f), mnA, sA, rA);
                int q3 = qidx(fmaxf(__fmaf_rn(e3, i3, o3), 0.f), mnA, sA, rA);
                w[px][cc] = (u32)q0 | ((u32)q1<<8) | ((u32)q2<<16) | ((u32)q3<<24);
                lsum[px] += q0 + q1 + q2 + q3;
            }
        }
        #pragma unroll
        for (int px = 0; px < 4; px++){
            u32* row = &As[(pxb+px)*132 + cig*8];
            *(uint4*)(row)     = make_uint4(w[px][0], w[px][1], w[px][2], w[px][3]);
            *(uint4*)(row + 4) = make_uint4(w[px][4], w[px][5], w[px][6], w[px][7]);
            atomicAdd(&rs_s[pxb+px], lsum[px]);
        }
    }
    __syncthreads();

    // ---- IMMA mainloop: warp computes 16px x 64co ----
    int r0 = (wid >> 1) * 16;
    int c0 = (wid & 1) * 64;
    int acc[8][4];
    #pragma unroll
    for (int ct = 0; ct < 8; ct++)
        #pragma unroll
        for (int d = 0; d < 4; d++) acc[ct][d] = 0;

    #pragma unroll 4
    for (int kk = 0; kk < 16; kk++){
        int kg0 = kk*8;
        u32 a0 = As[(r0 + g)*132     + kg0 + tg];
        u32 a1 = As[(r0 + 8 + g)*132 + kg0 + tg];
        u32 a2 = As[(r0 + g)*132     + kg0 + 4 + tg];
        u32 a3 = As[(r0 + 8 + g)*132 + kg0 + 4 + tg];
        #pragma unroll
        for (int ct = 0; ct < 8; ct++){
            int co = c0 + ct*8 + g;
            u32 b0 = Ws[co*132 + kg0 + tg];
            u32 b1 = Ws[co*132 + kg0 + 4 + tg];
            imma(acc[ct], a0, a1, a2, a3, b0, b1);
        }
    }
    __syncthreads();

    // ---- epilogue ----
    float mnW = g_qp[3], sW = g_qp[4];
    float SS = sA * sW;
    float c0f = 512.0f * mnA * mnW;
    float* fo = (float*)As;
    float lmin = 3.4e38f, lmax = -3.4e38f;
    #pragma unroll
    for (int hh = 0; hh < 2; hh++){
        int px = r0 + hh*8 + g;
        float t1 = __fmaf_rn(sA*mnW, (float)rs_s[px], c0f);
        #pragma unroll
        for (int ct = 0; ct < 8; ct++){
            #pragma unroll
            for (int e = 0; e < 2; e++){
                int co = c0 + ct*8 + 2*tg + e;
                float h = __fmaf_rn(SS, (float)acc[ct][hh*2+e],
                          __fmaf_rn(mnA*sW, (float)ws_s[co], t1));
                float a2v = fmaxf(__fmaf_rn(h, inv2[co], bia2[co]), 0.f);
                fo[px*132 + co] = a2v;
                lmin = fminf(lmin, a2v); lmax = fmaxf(lmax, a2v);
            }
        }
    }
    u32 emin = __reduce_min_sync(0xffffffffu, fenc(lmin));
    u32 emax = __reduce_max_sync(0xffffffffu, fenc(lmax));
    if (lane == 0){ red[wid] = emin; red[8+wid] = emax; }
    __syncthreads();
    if (tid == 0){
        u32 mn = red[0], mx = red[8];
        for (int i = 1; i < 8; i++){ mn = min(mn, red[i]); mx = max(mx, red[8+i]); }
        atomicMin(&g_mm[6], mn); atomicMax(&g_mm[7], mx);
    }
    #pragma unroll
    for (int it = 0; it < 8; it++){
        int f = it*256 + tid;
        int pxi = f >> 5, j = f & 31;
        float4 v = *(float4*)&fo[pxi*132 + j*4];
        *(float4*)&g_a2[(size_t)(p0 + pxi)*C2 + j*4] = v;
    }
}

// ---------------- K4: quantize a2 (4 pixels per warp, MLP=4) ----------------
__global__ void k_qa2(){
    int warp = threadIdx.x >> 5, lane = threadIdx.x & 31;
    int p = blockIdx.x*32 + warp*4;
    float mn = fdec(g_mm[6]), mx = fdec(g_mm[7]);
    float s = fmaxf(__fdiv_rn(mx - mn, 255.0f), 1e-8f), r = __frcp_rn(s);
    float4 v0 = ((const float4*)&g_a2[(size_t)(p+0)*C2])[lane];
    float4 v1 = ((const float4*)&g_a2[(size_t)(p+1)*C2])[lane];
    float4 v2 = ((const float4*)&g_a2[(size_t)(p+2)*C2])[lane];
    float4 v3 = ((const float4*)&g_a2[(size_t)(p+3)*C2])[lane];
    int q00=qidx(v0.x,mn,s,r), q01=qidx(v0.y,mn,s,r), q02=qidx(v0.z,mn,s,r), q03=qidx(v0.w,mn,s,r);
    int q10=qidx(v1.x,mn,s,r), q11=qidx(v1.y,mn,s,r), q12=qidx(v1.z,mn,s,r), q13=qidx(v1.w,mn,s,r);
    int q20=qidx(v2.x,mn,s,r), q21=qidx(v2.y,mn,s,r), q22=qidx(v2.z,mn,s,r), q23=qidx(v2.w,mn,s,r);
    int q30=qidx(v3.x,mn,s,r), q31=qidx(v3.y,mn,s,r), q32=qidx(v3.z,mn,s,r), q33=qidx(v3.w,mn,s,r);
    g_aq2[(size_t)(p+0)*32 + lane] = (u32)q00 | ((u32)q01<<8) | ((u32)q02<<16) | ((u32)q03<<24);
    g_aq2[(size_t)(p+1)*32 + lane] = (u32)q10 | ((u32)q11<<8) | ((u32)q12<<16) | ((u32)q13<<24);
    g_aq2[(size_t)(p+2)*32 + lane] = (u32)q20 | ((u32)q21<<8) | ((u32)q22<<16) | ((u32)q23<<24);
    g_aq2[(size_t)(p+3)*32 + lane] = (u32)q30 | ((u32)q31<<8) | ((u32)q32<<16) | ((u32)q33<<24);
    int s0 = __reduce_add_sync(0xffffffffu, q00+q01+q02+q03);
    int s1 = __reduce_add_sync(0xffffffffu, q10+q11+q12+q13);
    int s2 = __reduce_add_sync(0xffffffffu, q20+q21+q22+q23);
    int s3 = __reduce_add_sync(0xffffffffu, q30+q31+q32+q33);
    if (lane == 0){
        g_rs2[p+0] = s0; g_rs2[p+1] = s1; g_rs2[p+2] = s2; g_rs2[p+3] = s3;
    }
}

// ---------------- K5: 3x3 conv via IMMA, 4 output rows per block ----------------
#define AT2_ROWS 186   // 6*30 input rows + slack for discarded m=28..31 fragment reads
__global__ __launch_bounds__(256) void k_conv2(float* __restrict__ out){
    __shared__ u32 Ws[32*292];          // [co][288 words], stride 292
    __shared__ u32 a_t[AT2_ROWS*36];    // [6 rows x 30 halo cols][32 words], stride 36
    __shared__ int   rs_s[6*30];
    __shared__ float rsum_p[4][28];
    __shared__ float wvL[4][32], wvM[4][32], wvR[4][32];

    int tid = threadIdx.x;
    int b = blockIdx.x;
    int n = b / 7, hp = b % 7, h0 = hp*4;
    int wid = tid >> 5, lane = tid & 31;
    int g = lane >> 2, tg = lane & 3;

    for (int f = tid; f < 9216; f += 256){
        int co = f / 288, k = f - co*288;
        Ws[co*292 + k] = g_wq2c[f];
    }
    for (int f = tid; f < AT2_ROWS*36; f += 256) a_t[f] = 0;
    if (tid < 180) rs_s[tid] = 0;
    __syncthreads();
    for (int f = tid; f < 6*28*32; f += 256){
        int rr = f / (28*32); int rem = f - rr*28*32;
        int col = rem >> 5, k = rem & 31;
        int gh = h0 + rr - 1;
        if ((unsigned)gh < 28u)
            a_t[(rr*30 + col + 1)*36 + k] = g_aq2[(size_t)(n*HW + gh*28 + col)*32 + k];
    }
    if (tid < 168){
        int rr = tid / 28, col = tid % 28;
        int gh = h0 + rr - 1;
        if ((unsigned)gh < 28u) rs_s[rr*30 + col + 1] = g_rs2[n*HW + gh*28 + col];
    }
    __syncthreads();

    if (tid < 112){
        int orow = tid / 28, px = tid % 28;
        int ssum = 0;
        #pragma unroll
        for (int rr = 0; rr < 3; rr++)
            #pragma unroll
            for (int dw = 0; dw < 3; dw++)
                ssum += rs_s[(orow + rr)*30 + px + dw];
        rsum_p[orow][px] = (float)ssum;
    }
    if (tid >= 128){
        int t2 = tid - 128;
        int orow = t2 >> 5, co = t2 & 31;
        int h = h0 + orow;
        float m = 0.f, l = 0.f, r_ = 0.f;
        #pragma unroll
        for (int rr = 0; rr < 3; rr++){
            if ((unsigned)(h + rr - 1) < 28u){
                float w0 = (float)g_wts2[co*9 + rr*3 + 0];
                float w1 = (float)g_wts2[co*9 + rr*3 + 1];
                float w2 = (float)g_wts2[co*9 + rr*3 + 2];
                m  += w0 + w1 + w2;
                l  += w1 + w2;
                r_ += w0 + w1;
            }
        }
        wvM[orow][co] = m; wvL[orow][co] = l; wvR[orow][co] = r_;
    }
    __syncthreads();

    int orow = wid >> 1, cb = wid & 1;
    int acc[2][2][4];
    #pragma unroll
    for (int i = 0; i < 2; i++)
        #pragma unroll
        for (int j = 0; j < 2; j++)
            #pragma unroll
            for (int d = 0; d < 4; d++) acc[i][j][d] = 0;

    #pragma unroll
    for (int s = 0; s < 36; s++){
        int tap = s >> 2;
        int rr = tap / 3, dw = tap - rr*3;
        int w0 = (s & 3)*8 + tg;
        int rbase = (orow + rr)*30 + dw;
        u32 a0 = a_t[(rbase + g)*36      + w0];
        u32 a1 = a_t[(rbase + 8 + g)*36  + w0];
        u32 a2 = a_t[(rbase + g)*36      + w0 + 4];
        u32 a3 = a_t[(rbase + 8 + g)*36  + w0 + 4];
        u32 c0 = a_t[(rbase + 16 + g)*36 + w0];
        u32 c1 = a_t[(rbase + 24 + g)*36 + w0];
        u32 c2 = a_t[(rbase + 16 + g)*36 + w0 + 4];
        u32 c3 = a_t[(rbase + 24 + g)*36 + w0 + 4];
        #pragma unroll
        for (int cg = 0; cg < 2; cg++){
            int co = cb*16 + cg*8 + g;
            u32 b0 = Ws[co*292 + s*8 + tg];
            u32 b1 = Ws[co*292 + s*8 + 4 + tg];
            imma(acc[0][cg], a0, a1, a2, a3, b0, b1);
            imma(acc[1][cg], c0, c1, c2, c3, b0, b1);
        }
    }

    float mnA2 = fdec(g_mm[6]), mxA2 = fdec(g_mm[7]);
    float sA2 = fmaxf(__fdiv_rn(mxA2 - mnA2, 255.0f), 1e-8f);
    float mnW = g_qp[6], sW = g_qp[7];
    int h = h0 + orow;
    float rowv = 0.f;
    #pragma unroll
    for (int rr = 0; rr < 3; rr++) rowv += ((unsigned)(h + rr - 1) < 28u) ? 1.f : 0.f;
    float SS = sA2 * sW;
    #pragma unroll
    for (int ti = 0; ti < 2; ti++){
        #pragma unroll
        for (int hh = 0; hh < 2; hh++){
            int px = ti*16 + hh*8 + g;
            if (px < 28){
                float colv = (px == 0 || px == 27) ? 2.f : 3.f;
                float nv   = rowv * colv * 128.0f;
                float rp   = rsum_p[orow][px];
                #pragma unroll
                for (int cg = 0; cg < 2; cg++){
                    #pragma unroll
                    for (int e = 0; e < 2; e++){
                        int co = cb*16 + cg*8 + 2*tg + e;
                        float wvv = (px == 0) ? wvL[orow][co] : ((px == 27) ? wvR[orow][co] : wvM[orow][co]);
                        float o = __fmaf_rn(SS, (float)acc[ti][cg][hh*2+e],
                                  __fmaf_rn(sA2*mnW, rp,
                                  __fmaf_rn(mnA2*sW, wvv, mnA2*mnW*nv)));
                        out[((size_t)n*32 + co)*HW + h*28 + px] = o;
                    }
                }
            }
        }
    }
}

extern "C" void kernel_launch(void* const* d_in, const int* in_sizes, int n_in,
                              void* d_out, int out_size){
    const float* x  = (const float*)d_in[0];
    const float* g1 = (const float*)d_in[1];
    const float* b1 = (const float*)d_in[2];
    const float* m1 = (const float*)d_in[3];
    const float* v1 = (const float*)d_in[4];
    const float* w1 = (const float*)d_in[5];
    const float* g2 = (const float*)d_in[6];
    const float* b2 = (const float*)d_in[7];
    const float* m2 = (const float*)d_in[8];
    const float* v2 = (const float*)d_in[9];
    const float* w2 = (const float*)d_in[10];
    float* out = (float*)d_out;

    cudaFuncSetAttribute(k_conv1, cudaFuncAttributeMaxDynamicSharedMemorySize, DYN_SMEM);

    k_mm   <<<528, 256>>>(x, w1, w2);
    k_prep <<<161, 256>>>(w1, w2, g1, b1, m1, v1);
    k_conv1<<<784, 256, DYN_SMEM>>>(x, g1, b1, m1, v1, g2, b2, m2, v2);
    k_qa2  <<<1568, 256>>>();
    k_conv2<<<448, 256>>>(out);
}